// round 15
// baseline (speedup 1.0000x reference)
#include <cuda_runtime.h>
#include <cuda_bf16.h>
#include <cuda_fp16.h>
#include <math.h>
#include <stdint.h>

#define HIDDEN 4096
#define NHEADS 16
#define HDIM   256
#define ROT    64
#define BATCH  2
#define SEQ    2048
#define MROWS  (BATCH*SEQ)   /* 4096 */

// scratch slots (each 4096*4096 16-bit = 32 MB)
// 0:Xh(fp16) 1:Xl(fp16) 2:Oh(fp16) 3:Ol(fp16)
// 4-6:WqkvH(fp16) 7-9:WqkvL(fp16) 10:Wo(fp16) 11:unused
// 12:Qh 13:Ql 14:Kh 15:Kl (bf16)  16:Vh 17:Vl (fp16)
__device__ __nv_bfloat16 g_bf16[18ull * MROWS * HIDDEN];

#define SLOT ((size_t)MROWS * HIDDEN)

// inv_freq[j] = 10000^(-j/32) = 10^(-j/8), j = 0..31
__constant__ double d_invfreq[32] = {
    1.0,                    0.7498942093324559,    0.5623413251903491,
    0.42169650342858224,    0.31622776601683794,   0.23713737056616552,
    0.17782794100389228,    0.13335214321633242,   0.1,
    0.07498942093324558,    0.05623413251903491,   0.042169650342858224,
    0.03162277660168379,    0.023713737056616554,  0.017782794100389228,
    0.01333521432163324,    0.01,                  0.007498942093324559,
    0.005623413251903491,   0.004216965034285822,  0.0031622776601683794,
    0.0023713737056616554,  0.0017782794100389228, 0.0013335214321633241,
    0.001,                  0.0007498942093324558, 0.0005623413251903491,
    0.00042169650342858227, 0.00031622776601683794,0.00023713737056616552,
    0.00017782794100389227, 0.00013335214321633242
};

// ============================================================================
// PTX helpers
// ============================================================================
__device__ __forceinline__ uint32_t smem_u32(const void* p) {
    uint32_t a;
    asm("{ .reg .u64 t; cvta.to.shared.u64 t, %1; cvt.u32.u64 %0, t; }"
        : "=r"(a) : "l"(p));
    return a;
}

__device__ __forceinline__ void cp_async16(uint32_t dst, const void* src) {
    asm volatile("cp.async.cg.shared.global [%0], [%1], 16;"
                 :: "r"(dst), "l"(src));
}
#define CP_COMMIT() asm volatile("cp.async.commit_group;" ::: "memory")
#define CP_WAIT(n)  asm volatile("cp.async.wait_group %0;" :: "n"(n) : "memory")

__device__ __forceinline__ void ldsm_x4(uint32_t& r0, uint32_t& r1,
                                        uint32_t& r2, uint32_t& r3,
                                        uint32_t addr) {
    asm volatile("ldmatrix.sync.aligned.m8n8.x4.shared.b16 {%0,%1,%2,%3}, [%4];"
                 : "=r"(r0), "=r"(r1), "=r"(r2), "=r"(r3) : "r"(addr));
}
__device__ __forceinline__ void ldsm_x4_t(uint32_t& r0, uint32_t& r1,
                                          uint32_t& r2, uint32_t& r3,
                                          uint32_t addr) {
    asm volatile("ldmatrix.sync.aligned.m8n8.x4.trans.shared.b16 {%0,%1,%2,%3}, [%4];"
                 : "=r"(r0), "=r"(r1), "=r"(r2), "=r"(r3) : "r"(addr));
}

__device__ __forceinline__ void mma_bf16(float c[4],
                                         uint32_t a0, uint32_t a1,
                                         uint32_t a2, uint32_t a3,
                                         uint32_t b0, uint32_t b1) {
    asm volatile(
        "mma.sync.aligned.m16n8k16.row.col.f32.bf16.bf16.f32 "
        "{%0,%1,%2,%3}, {%4,%5,%6,%7}, {%8,%9}, {%0,%1,%2,%3};"
        : "+f"(c[0]), "+f"(c[1]), "+f"(c[2]), "+f"(c[3])
        : "r"(a0), "r"(a1), "r"(a2), "r"(a3), "r"(b0), "r"(b1));
}

__device__ __forceinline__ void mma_fp16(float c[4],
                                         uint32_t a0, uint32_t a1,
                                         uint32_t a2, uint32_t a3,
                                         uint32_t b0, uint32_t b1) {
    asm volatile(
        "mma.sync.aligned.m16n8k16.row.col.f32.f16.f16.f32 "
        "{%0,%1,%2,%3}, {%4,%5,%6,%7}, {%8,%9}, {%0,%1,%2,%3};"
        : "+f"(c[0]), "+f"(c[1]), "+f"(c[2]), "+f"(c[3])
        : "r"(a0), "r"(a1), "r"(a2), "r"(a3), "r"(b0), "r"(b1));
}

__device__ __forceinline__ uint32_t pack_bf16(float a, float b) {
    __nv_bfloat162 t = __floats2bfloat162_rn(a, b);
    return *(uint32_t*)&t;
}
__device__ __forceinline__ uint32_t pack_half(float a, float b) {
    __half2 t = __floats2half2_rn(a, b);
    return *(uint32_t*)&t;
}

// ============================================================================
// Fused split kernel: z=0..2 -> Wq/Wk/Wv transpose+split(fp16 hi/lo),
// z=3 -> Wo transpose+round(fp16 single), z=4 -> X row split(fp16 hi/lo).
// ============================================================================
__global__ __launch_bounds__(256) void split_all_kernel(
    const float* __restrict__ X,
    const float* __restrict__ Wq, const float* __restrict__ Wk,
    const float* __restrict__ Wv, const float* __restrict__ Wo,
    __half* __restrict__ Xh, __half* __restrict__ Xl,
    __half* __restrict__ WqkvH, __half* __restrict__ WqkvL,
    __half* __restrict__ Wo16)
{
    const int z = blockIdx.z;
    if (z == 4) {
        size_t blk = (size_t)blockIdx.y * 128 + blockIdx.x;
        size_t i = (blk * 256 + threadIdx.x) * 4;
        float4 v = *(const float4*)(X + i);
        float f[4] = {v.x, v.y, v.z, v.w};
        __half hh[4], ll[4];
        #pragma unroll
        for (int j = 0; j < 4; j++) {
            hh[j] = __float2half_rn(f[j]);
            ll[j] = __float2half_rn(f[j] - __half2float(hh[j]));
        }
        *(uint2*)(Xh + i) = *(uint2*)hh;
        *(uint2*)(Xl + i) = *(uint2*)ll;
        return;
    }

    __shared__ float t[32][33];
    const float* W;
    __half *H = nullptr, *L = nullptr;
    if (z == 0)      { W = Wq; H = WqkvH;                         L = WqkvL; }
    else if (z == 1) { W = Wk; H = WqkvH + (size_t)4096 * HIDDEN; L = WqkvL + (size_t)4096 * HIDDEN; }
    else if (z == 2) { W = Wv; H = WqkvH + (size_t)8192 * HIDDEN; L = WqkvL + (size_t)8192 * HIDDEN; }
    else             { W = Wo; }

    const int n0 = blockIdx.x * 32;
    const int k0 = blockIdx.y * 32;
    const int tx = threadIdx.x & 31;
    const int ty = threadIdx.x >> 5;
    #pragma unroll
    for (int j = ty; j < 32; j += 8)
        t[j][tx] = W[(size_t)(k0 + j) * HIDDEN + n0 + tx];
    __syncthreads();
    #pragma unroll
    for (int j = ty; j < 32; j += 8) {
        float x = t[tx][j];
        size_t off = (size_t)(n0 + j) * HIDDEN + k0 + tx;
        if (z == 3) {
            Wo16[off] = __float2half_rn(x);
        } else {
            __half h = __float2half_rn(x);
            __half l = __float2half_rn(x - __half2float(h));
            H[off] = h;
            L[off] = l;
        }
    }
}

// ============================================================================
// QKV GEMM, fp16: 3-term (hh,lh,hl) for Q/K regions, 2-term (hh,lh) for V.
// CTA 128x128, BK=32, 8 warps 64x32, 2 CTA/SM, single barrier per iter.
// ============================================================================
#define GBK     32
#define TILE_B  10240
#define STAGE_B (4 * TILE_B)

__global__ __launch_bounds__(256, 2) void gemm_qkv_kernel(
    const __half* __restrict__ Ah, const __half* __restrict__ Al,
    const __half* __restrict__ Bh, const __half* __restrict__ Bl,
    const int* __restrict__ pos_ids,
    __nv_bfloat16* __restrict__ Qh, __nv_bfloat16* __restrict__ Ql,
    __nv_bfloat16* __restrict__ Kh, __nv_bfloat16* __restrict__ Kl,
    __half* __restrict__ Vh, __half* __restrict__ Vl)
{
    extern __shared__ char smg[];
    const uint32_t sb = smem_u32(smg);
    const int tid  = threadIdx.x;
    const int wid  = tid >> 5;
    const int lane = tid & 31;
    const int wm = wid >> 2;
    const int wn = wid & 3;
    const int rowbase = blockIdx.y * 128;
    const int colbase = blockIdx.x * 128;
    const int region = colbase >> 12;          // 0=Q, 1=K, 2=V
    const bool term3 = (region < 2);           // V region: 2-term

    const __half* bases[4];
    bases[0] = Ah + (size_t)rowbase * HIDDEN;
    bases[1] = Al + (size_t)rowbase * HIDDEN;
    bases[2] = Bh + (size_t)colbase * HIDDEN;
    bases[3] = Bl + (size_t)colbase * HIDDEN;

    const int arow = lane & 15;
    const int aoff = ((lane >> 4) & 1) * 16;
    const int brow = (lane & 7) + ((lane >> 4) & 1) * 8;
    const int boff = ((lane >> 3) & 1) * 16;

    float acc[4][4][4];
    #pragma unroll
    for (int i = 0; i < 4; i++)
        #pragma unroll
        for (int j = 0; j < 4; j++)
            #pragma unroll
            for (int q = 0; q < 4; q++) acc[i][j][q] = 0.0f;

    const int NCH = HIDDEN / GBK;
    {
        #pragma unroll
        for (int it = 0; it < 8; it++) {
            int t = tid + it * 256;
            int tile = t >> 9;
            int r    = (t >> 2) & 127;
            int ch   = t & 3;
            const void* gp = bases[tile] + (size_t)r * HIDDEN + ch * 8;
            uint32_t d = sb + tile * TILE_B + r * 80 + ch * 16;
            cp_async16(d, gp);
        }
        CP_COMMIT();
    }
    for (int c = 0; c < NCH; c++) {
        const int p = c & 1;
        CP_WAIT(0);
        __syncthreads();
        if (c + 1 < NCH) {
            const int kb = (c + 1) * GBK;
            #pragma unroll
            for (int it = 0; it < 8; it++) {
                int t = tid + it * 256;
                int tile = t >> 9;
                int r    = (t >> 2) & 127;
                int ch   = t & 3;
                const void* gp = bases[tile] + (size_t)r * HIDDEN + kb + ch * 8;
                uint32_t d = sb + (p ^ 1) * STAGE_B + tile * TILE_B + r * 80 + ch * 16;
                cp_async16(d, gp);
            }
            CP_COMMIT();
        }
        const uint32_t At_h = sb + p * STAGE_B;
        const uint32_t At_l = At_h + TILE_B;
        const uint32_t Bt_h = At_h + 2 * TILE_B;
        const uint32_t Bt_l = At_h + 3 * TILE_B;
        #pragma unroll
        for (int ks = 0; ks < 2; ks++) {
            const int kbyte = ks * 32;
            uint32_t ah[4][4], al[4][4];
            #pragma unroll
            for (int mi = 0; mi < 4; mi++) {
                ldsm_x4(ah[mi][0], ah[mi][1], ah[mi][2], ah[mi][3],
                        At_h + (wm * 64 + mi * 16 + arow) * 80 + kbyte + aoff);
                ldsm_x4(al[mi][0], al[mi][1], al[mi][2], al[mi][3],
                        At_l + (wm * 64 + mi * 16 + arow) * 80 + kbyte + aoff);
            }
            uint32_t bh[4][2], bl[4][2];
            #pragma unroll
            for (int nf2 = 0; nf2 < 2; nf2++) {
                uint32_t r0, r1, r2, r3;
                ldsm_x4(r0, r1, r2, r3,
                        Bt_h + (wn * 32 + nf2 * 16 + brow) * 80 + kbyte + boff);
                bh[nf2 * 2][0] = r0; bh[nf2 * 2][1] = r1;
                bh[nf2 * 2 + 1][0] = r2; bh[nf2 * 2 + 1][1] = r3;
                ldsm_x4(r0, r1, r2, r3,
                        Bt_l + (wn * 32 + nf2 * 16 + brow) * 80 + kbyte + boff);
                bl[nf2 * 2][0] = r0; bl[nf2 * 2][1] = r1;
                bl[nf2 * 2 + 1][0] = r2; bl[nf2 * 2 + 1][1] = r3;
            }
            #pragma unroll
            for (int mi = 0; mi < 4; mi++)
                #pragma unroll
                for (int nf = 0; nf < 4; nf++) {
                    mma_fp16(acc[mi][nf], ah[mi][0], ah[mi][1], ah[mi][2], ah[mi][3], bh[nf][0], bh[nf][1]);
                    mma_fp16(acc[mi][nf], al[mi][0], al[mi][1], al[mi][2], al[mi][3], bh[nf][0], bh[nf][1]);
                    if (term3)
                        mma_fp16(acc[mi][nf], ah[mi][0], ah[mi][1], ah[mi][2], ah[mi][3], bl[nf][0], bl[nf][1]);
                }
        }
    }

    const int ncolbase = colbase & 4095;
    const int g = lane >> 2;
    const int t4 = lane & 3;
    const bool rotwarp = (region < 2) && ((colbase & 255) == 0) && (wn < 2);

    double invd[4];
    if (rotwarp) {
        #pragma unroll
        for (int nf = 0; nf < 4; nf++)
            invd[nf] = d_invfreq[wn * 16 + nf * 4 + t4];
    }
    const float qscale = (region == 0) ? 0.0625f : 1.0f;
    __nv_bfloat16 *H = (region == 0) ? Qh : Kh;
    __nv_bfloat16 *L = (region == 0) ? Ql : Kl;

    #pragma unroll
    for (int mi = 0; mi < 4; mi++) {
        const int rA = rowbase + wm * 64 + mi * 16 + g;
        const int rB = rA + 8;
        int posA = 0, posB = 0;
        if (rotwarp) { posA = pos_ids[rA]; posB = pos_ids[rB]; }
        #pragma unroll
        for (int nf = 0; nf < 4; nf++) {
            float v0 = acc[mi][nf][0], v1 = acc[mi][nf][1];
            float v2 = acc[mi][nf][2], v3 = acc[mi][nf][3];
            if (rotwarp) {
                float angA = (float)((double)posA * invd[nf]);
                float angB = (float)((double)posB * invd[nf]);
                float sA = sinf(angA), cA = cosf(angA);
                float sB = sinf(angB), cB = cosf(angB);
                float t0 = v0 * cA - v1 * sA;
                float t1 = v1 * cA + v0 * sA;
                v0 = t0; v1 = t1;
                t0 = v2 * cB - v3 * sB;
                t1 = v3 * cB + v2 * sB;
                v2 = t0; v3 = t1;
            }
            v0 *= qscale; v1 *= qscale; v2 *= qscale; v3 *= qscale;

            size_t ncol = (size_t)(ncolbase + wn * 32 + nf * 8 + t4 * 2);
            size_t offA = (size_t)rA * HIDDEN + ncol;
            size_t offB = (size_t)rB * HIDDEN + ncol;

            if (region == 2) {
                __half h0 = __float2half_rn(v0), h1 = __float2half_rn(v1);
                __half h2 = __float2half_rn(v2), h3 = __float2half_rn(v3);
                float l0 = v0 - __half2float(h0), l1 = v1 - __half2float(h1);
                float l2 = v2 - __half2float(h2), l3 = v3 - __half2float(h3);
                *(uint32_t*)(Vh + offA) = pack_half(__half2float(h0), __half2float(h1));
                *(uint32_t*)(Vl + offA) = pack_half(l0, l1);
                *(uint32_t*)(Vh + offB) = pack_half(__half2float(h2), __half2float(h3));
                *(uint32_t*)(Vl + offB) = pack_half(l2, l3);
            } else {
                __nv_bfloat16 h0 = __float2bfloat16(v0), h1 = __float2bfloat16(v1);
                __nv_bfloat16 h2 = __float2bfloat16(v2), h3 = __float2bfloat16(v3);
                float l0 = v0 - __bfloat162float(h0), l1 = v1 - __bfloat162float(h1);
                float l2 = v2 - __bfloat162float(h2), l3 = v3 - __bfloat162float(h3);
                *(uint32_t*)(H + offA) = pack_bf16(__bfloat162float(h0), __bfloat162float(h1));
                *(uint32_t*)(L + offA) = pack_bf16(l0, l1);
                *(uint32_t*)(H + offB) = pack_bf16(__bfloat162float(h2), __bfloat162float(h3));
                *(uint32_t*)(L + offB) = pack_bf16(l2, l3);
            }
        }
    }
}

// ============================================================================
// Wo GEMM, fp16 2-term (unchanged from R14)
// ============================================================================
#define WO_STAGE (3 * TILE_B)

__global__ __launch_bounds__(256, 2) void gemm_wo_fp16_kernel(
    const __half* __restrict__ Ah, const __half* __restrict__ Al,
    const __half* __restrict__ Bh, float* __restrict__ C)
{
    extern __shared__ char smg[];
    const uint32_t sb = smem_u32(smg);
    const int tid  = threadIdx.x;
    const int wid  = tid >> 5;
    const int lane = tid & 31;
    const int wm = wid >> 2;
    const int wn = wid & 3;
    const int rowbase = blockIdx.y * 128;
    const int colbase = blockIdx.x * 128;

    const __half* bases[3];
    bases[0] = Ah + (size_t)rowbase * HIDDEN;
    bases[1] = Al + (size_t)rowbase * HIDDEN;
    bases[2] = Bh + (size_t)colbase * HIDDEN;

    const int arow = lane & 15;
    const int aoff = ((lane >> 4) & 1) * 16;
    const int brow = (lane & 7) + ((lane >> 4) & 1) * 8;
    const int boff = ((lane >> 3) & 1) * 16;

    float acc[4][4][4];
    #pragma unroll
    for (int i = 0; i < 4; i++)
        #pragma unroll
        for (int j = 0; j < 4; j++)
            #pragma unroll
            for (int q = 0; q < 4; q++) acc[i][j][q] = 0.0f;

    const int NCH = HIDDEN / GBK;
    {
        #pragma unroll
        for (int it = 0; it < 6; it++) {
            int t = tid + it * 256;
            int tile = t >> 9;
            int r    = (t >> 2) & 127;
            int ch   = t & 3;
            const void* gp = bases[tile] + (size_t)r * HIDDEN + ch * 8;
            uint32_t d = sb + tile * TILE_B + r * 80 + ch * 16;
            cp_async16(d, gp);
        }
        CP_COMMIT();
    }
    for (int c = 0; c < NCH; c++) {
        const int p = c & 1;
        CP_WAIT(0);
        __syncthreads();
        if (c + 1 < NCH) {
            const int kb = (c + 1) * GBK;
            #pragma unroll
            for (int it = 0; it < 6; it++) {
                int t = tid + it * 256;
                int tile = t >> 9;
                int r    = (t >> 2) & 127;
                int ch   = t & 3;
                const void* gp = bases[tile] + (size_t)r * HIDDEN + kb + ch * 8;
                uint32_t d = sb + (p ^ 1) * WO_STAGE + tile * TILE_B + r * 80 + ch * 16;
                cp_async16(d, gp);
            }
            CP_COMMIT();
        }
        const uint32_t At_h = sb + p * WO_STAGE;
        const uint32_t At_l = At_h + TILE_B;
        const uint32_t Bt_h = At_h + 2 * TILE_B;
        #pragma unroll
        for (int ks = 0; ks < 2; ks++) {
            const int kbyte = ks * 32;
            uint32_t ah[4][4], al[4][4];
            #pragma unroll
            for (int mi = 0; mi < 4; mi++) {
                ldsm_x4(ah[mi][0], ah[mi][1], ah[mi][2], ah[mi][3],
                        At_h + (wm * 64 + mi * 16 + arow) * 80 + kbyte + aoff);
                ldsm_x4(al[mi][0], al[mi][1], al[mi][2], al[mi][3],
                        At_l + (wm * 64 + mi * 16 + arow) * 80 + kbyte + aoff);
            }
            uint32_t bh[4][2];
            #pragma unroll
            for (int nf2 = 0; nf2 < 2; nf2++) {
                uint32_t r0, r1, r2, r3;
                ldsm_x4(r0, r1, r2, r3,
                        Bt_h + (wn * 32 + nf2 * 16 + brow) * 80 + kbyte + boff);
                bh[nf2 * 2][0] = r0; bh[nf2 * 2][1] = r1;
                bh[nf2 * 2 + 1][0] = r2; bh[nf2 * 2 + 1][1] = r3;
            }
            #pragma unroll
            for (int mi = 0; mi < 4; mi++)
                #pragma unroll
                for (int nf = 0; nf < 4; nf++) {
                    mma_fp16(acc[mi][nf], ah[mi][0], ah[mi][1], ah[mi][2], ah[mi][3], bh[nf][0], bh[nf][1]);
                    mma_fp16(acc[mi][nf], al[mi][0], al[mi][1], al[mi][2], al[mi][3], bh[nf][0], bh[nf][1]);
                }
        }
    }

    const int g = lane >> 2;
    const int t = lane & 3;
    #pragma unroll
    for (int mi = 0; mi < 4; mi++) {
        #pragma unroll
        for (int nf = 0; nf < 4; nf++) {
            float* base = C + (size_t)(rowbase + wm * 64 + mi * 16 + g) * HIDDEN
                            + colbase + wn * 32 + nf * 8 + t * 2;
            *(float2*)base = make_float2(acc[mi][nf][0], acc[mi][nf][1]);
            *(float2*)(base + (size_t)8 * HIDDEN) = make_float2(acc[mi][nf][2], acc[mi][nf][3]);
        }
    }
}

// ============================================================================
// Flash attention: QK bf16x3 (amplified path, full precision);
// P fp16-single; V fp16 hi/lo; PV = 2 fp16 MMAs per V-half (4 per np).
// ============================================================================
#define AQ   64
#define AKV  64
#define QSTR 528
#define PSTR 144

#define A_QH 0
#define A_QL 33792
#define A_KH 67584
#define A_KL 101376
#define A_VH 135168
#define A_VL 168960
#define A_PH 202752
#define A_ST 221184
#define A_SMEM_TOTAL 223488

__global__ __launch_bounds__(256, 1) void attn_mma_kernel(
    const __nv_bfloat16* __restrict__ Qh_g, const __nv_bfloat16* __restrict__ Ql_g,
    const __nv_bfloat16* __restrict__ Kh_g, const __nv_bfloat16* __restrict__ Kl_g,
    const __half* __restrict__ Vh_g, const __half* __restrict__ Vl_g,
    const float* __restrict__ amask,
    __half* __restrict__ Oh, __half* __restrict__ Ol)
{
    extern __shared__ char sma[];
    const uint32_t sb = smem_u32(sma);
    float* pmax   = (float*)(sma + A_ST);
    float* psum   = (float*)(sma + A_ST + 512);
    float* mrow   = (float*)(sma + A_ST + 1024);
    float* lrow   = (float*)(sma + A_ST + 1280);
    float* corr   = (float*)(sma + A_ST + 1536);
    float* mnew   = (float*)(sma + A_ST + 1792);
    float* amask_s= (float*)(sma + A_ST + 2048);

    const int tid  = threadIdx.x;
    const int wid  = tid >> 5;
    const int lane = tid & 31;
    const int qg   = wid & 3;
    const int kvh  = wid >> 2;
    const int dh   = wid >> 2;
    const int qt   = (int)gridDim.x - 1 - (int)blockIdx.x;
    const int h    = blockIdx.y;
    const int b    = blockIdx.z;
    const int q0   = qt * AQ;

    const int g = lane >> 2;
    const int t4 = lane & 3;
    const int arow = lane & 15;
    const int aoff = ((lane >> 4) & 1) * 16;
    const int brow = (lane & 7) + ((lane >> 4) & 1) * 8;
    const int boff = ((lane >> 3) & 1) * 16;
    const int vrow = (lane & 7) + ((lane >> 3) & 1) * 8;
    const int vcoff = (lane >> 4) * 8;

    if (tid < 64) { mrow[tid] = -1e30f; lrow[tid] = 0.0f; }

    {
        const __nv_bfloat16* qh = Qh_g + (size_t)(b * SEQ + q0) * HIDDEN + h * 256;
        const __nv_bfloat16* ql = Ql_g + (size_t)(b * SEQ + q0) * HIDDEN + h * 256;
        #pragma unroll
        for (int it = 0; it < 8; it++) {
            int t = tid + it * 256;
            int r = t >> 5, c = t & 31;
            cp_async16(sb + A_QH + r * QSTR + c * 16, qh + (size_t)r * HIDDEN + c * 8);
            cp_async16(sb + A_QL + r * QSTR + c * 16, ql + (size_t)r * HIDDEN + c * 8);
        }
    }

    float o[16][4];
    #pragma unroll
    for (int i = 0; i < 16; i++)
        #pragma unroll
        for (int q = 0; q < 4; q++) o[i][q] = 0.0f;

    for (int kc = 0; kc <= qt; kc++) {
        const int k0 = kc * AKV;
        if (kc) __syncthreads();

        {
            const __nv_bfloat16* kh = Kh_g + (size_t)(b * SEQ + k0) * HIDDEN + h * 256;
            const __nv_bfloat16* kl = Kl_g + (size_t)(b * SEQ + k0) * HIDDEN + h * 256;
            #pragma unroll
            for (int it = 0; it < 8; it++) {
                int t = tid + it * 256;
                int r = t >> 5, c = t & 31;
                cp_async16(sb + A_KH + r * QSTR + c * 16, kh + (size_t)r * HIDDEN + c * 8);
                cp_async16(sb + A_KL + r * QSTR + c * 16, kl + (size_t)r * HIDDEN + c * 8);
            }
            CP_COMMIT();
        }
        {
            const __half* vh = Vh_g + (size_t)(b * SEQ + k0) * HIDDEN + h * 256;
            const __half* vl = Vl_g + (size_t)(b * SEQ + k0) * HIDDEN + h * 256;
            #pragma unroll
            for (int it = 0; it < 8; it++) {
                int t = tid + it * 256;
                int r = t >> 5, c = t & 31;
                cp_async16(sb + A_VH + r * QSTR + c * 16, vh + (size_t)r * HIDDEN + c * 8);
                cp_async16(sb + A_VL + r * QSTR + c * 16, vl + (size_t)r * HIDDEN + c * 8);
            }
            CP_COMMIT();
        }
        if (tid < 64) amask_s[tid] = amask[b * SEQ + k0 + tid];

        CP_WAIT(1);
        __syncthreads();

        float s[4][4];
        #pragma unroll
        for (int nt = 0; nt < 4; nt++)
            #pragma unroll
            for (int q = 0; q < 4; q++) s[nt][q] = 0.0f;

        #pragma unroll
        for (int ks = 0; ks < 16; ks++) {
            const int kb = ks * 32;
            uint32_t qah[4], qal[4];
            ldsm_x4(qah[0], qah[1], qah[2], qah[3],
                    sb + A_QH + (qg * 16 + arow) * QSTR + kb + aoff);
            ldsm_x4(qal[0], qal[1], qal[2], qal[3],
                    sb + A_QL + (qg * 16 + arow) * QSTR + kb + aoff);
            uint32_t kbh[4][2], kbl[4][2];
            #pragma unroll
            for (int n2 = 0; n2 < 2; n2++) {
                uint32_t r0, r1, r2, r3;
                ldsm_x4(r0, r1, r2, r3,
                        sb + A_KH + (kvh * 32 + n2 * 16 + brow) * QSTR + kb + boff);
                kbh[n2 * 2][0] = r0; kbh[n2 * 2][1] = r1;
                kbh[n2 * 2 + 1][0] = r2; kbh[n2 * 2 + 1][1] = r3;
                ldsm_x4(r0, r1, r2, r3,
                        sb + A_KL + (kvh * 32 + n2 * 16 + brow) * QSTR + kb + boff);
                kbl[n2 * 2][0] = r0; kbl[n2 * 2][1] = r1;
                kbl[n2 * 2 + 1][0] = r2; kbl[n2 * 2 + 1][1] = r3;
            }
            #pragma unroll
            for (int nt = 0; nt < 4; nt++) {
                mma_bf16(s[nt], qah[0], qah[1], qah[2], qah[3], kbh[nt][0], kbh[nt][1]);
                mma_bf16(s[nt], qah[0], qah[1], qah[2], qah[3], kbl[nt][0], kbl[nt][1]);
                mma_bf16(s[nt], qal[0], qal[1], qal[2], qal[3], kbh[nt][0], kbh[nt][1]);
            }
        }

        const int rA = q0 + qg * 16 + g;
        const int rB = rA + 8;
        #pragma unroll
        for (int nt = 0; nt < 4; nt++) {
            int lc = kvh * 32 + nt * 8 + t4 * 2;
            int cg = k0 + lc;
            bool p0 = amask_s[lc] > 0.0f;
            bool p1 = amask_s[lc + 1] > 0.0f;
            if (cg > rA || !p0)     s[nt][0] = -1e30f;
            if (cg + 1 > rA || !p1) s[nt][1] = -1e30f;
            if (cg > rB || !p0)     s[nt][2] = -1e30f;
            if (cg + 1 > rB || !p1) s[nt][3] = -1e30f;
        }

        float mA = -1e30f, mB = -1e30f;
        #pragma unroll
        for (int nt = 0; nt < 4; nt++) {
            mA = fmaxf(mA, fmaxf(s[nt][0], s[nt][1]));
            mB = fmaxf(mB, fmaxf(s[nt][2], s[nt][3]));
        }
        mA = fmaxf(mA, __shfl_xor_sync(0xffffffffu, mA, 1));
        mA = fmaxf(mA, __shfl_xor_sync(0xffffffffu, mA, 2));
        mB = fmaxf(mB, __shfl_xor_sync(0xffffffffu, mB, 1));
        mB = fmaxf(mB, __shfl_xor_sync(0xffffffffu, mB, 2));
        if (t4 == 0) {
            pmax[kvh * 64 + qg * 16 + g] = mA;
            pmax[kvh * 64 + qg * 16 + g + 8] = mB;
        }
        __syncthreads();

        if (tid < 64) {
            float mo = mrow[tid];
            float pm = fmaxf(pmax[tid], pmax[64 + tid]);
            float mn = fmaxf(mo, pm);
            mnew[tid] = mn;
            corr[tid] = __expf(mo - mn);
            mrow[tid] = mn;
        }
        __syncthreads();

        {
            float mnA = mnew[qg * 16 + g];
            float mnB = mnew[qg * 16 + g + 8];
            float sA = 0.0f, sB = 0.0f;
            #pragma unroll
            for (int nt = 0; nt < 4; nt++) {
                float p0 = __expf(s[nt][0] - mnA);
                float p1 = __expf(s[nt][1] - mnA);
                float p2 = __expf(s[nt][2] - mnB);
                float p3 = __expf(s[nt][3] - mnB);
                sA += p0 + p1;
                sB += p2 + p3;
                uint32_t cb = (kvh * 32 + nt * 8 + t4 * 2) * 2;
                uint32_t adrA = (qg * 16 + g) * PSTR + cb;
                uint32_t adrB = (qg * 16 + g + 8) * PSTR + cb;
                *(uint32_t*)(sma + A_PH + adrA) = pack_half(p0, p1);
                *(uint32_t*)(sma + A_PH + adrB) = pack_half(p2, p3);
            }
            sA += __shfl_xor_sync(0xffffffffu, sA, 1);
            sA += __shfl_xor_sync(0xffffffffu, sA, 2);
            sB += __shfl_xor_sync(0xffffffffu, sB, 1);
            sB += __shfl_xor_sync(0xffffffffu, sB, 2);
            if (t4 == 0) {
                psum[kvh * 64 + qg * 16 + g] = sA;
                psum[kvh * 64 + qg * 16 + g + 8] = sB;
            }
        }
        CP_WAIT(0);
        __syncthreads();

        if (tid < 64)
            lrow[tid] = lrow[tid] * corr[tid] + psum[tid] + psum[64 + tid];

        {
            float cA = corr[qg * 16 + g];
            float cB = corr[qg * 16 + g + 8];
            #pragma unroll
            for (int nt = 0; nt < 16; nt++) {
                o[nt][0] *= cA; o[nt][1] *= cA;
                o[nt][2] *= cB; o[nt][3] *= cB;
            }
        }
        #pragma unroll
        for (int ks = 0; ks < 4; ks++) {
            uint32_t pah[4];
            ldsm_x4(pah[0], pah[1], pah[2], pah[3],
                    sb + A_PH + (qg * 16 + arow) * PSTR + ks * 32 + aoff);
            #pragma unroll
            for (int np = 0; np < 8; np++) {
                int col = dh * 128 + np * 16 + vcoff;
                uint32_t vrowg = (ks * 16 + vrow) * QSTR + col * 2;
                uint32_t vh0, vh1, vh2, vh3, vl0, vl1, vl2, vl3;
                ldsm_x4_t(vh0, vh1, vh2, vh3, sb + A_VH + vrowg);
                ldsm_x4_t(vl0, vl1, vl2, vl3, sb + A_VL + vrowg);
                mma_fp16(o[np * 2], pah[0], pah[1], pah[2], pah[3], vh0, vh1);
                mma_fp16(o[np * 2], pah[0], pah[1], pah[2], pah[3], vl0, vl1);
                mma_fp16(o[np * 2 + 1], pah[0], pah[1], pah[2], pah[3], vh2, vh3);
                mma_fp16(o[np * 2 + 1], pah[0], pah[1], pah[2], pah[3], vl2, vl3);
            }
        }
    }

    __syncthreads();
    {
        float invA = 1.0f / lrow[qg * 16 + g];
        float invB = 1.0f / lrow[qg * 16 + g + 8];
        size_t rowA = (size_t)(b * SEQ + q0 + qg * 16 + g) * HIDDEN;
        size_t rowB = rowA + (size_t)8 * HIDDEN;
        int colbase = h * 256 + dh * 128 + t4 * 2;
        #pragma unroll
        for (int nt = 0; nt < 16; nt++) {
            int col = colbase + nt * 8;
            float a0 = o[nt][0] * invA, a1 = o[nt][1] * invA;
            float b0 = o[nt][2] * invB, b1 = o[nt][3] * invB;
            __half ha0 = __float2half_rn(a0), ha1 = __float2half_rn(a1);
            __half hb0 = __float2half_rn(b0), hb1 = __float2half_rn(b1);
            *(uint32_t*)(Oh + rowA + col) = pack_half(__half2float(ha0), __half2float(ha1));
            *(uint32_t*)(Ol + rowA + col) = pack_half(a0 - __half2float(ha0), a1 - __half2float(ha1));
            *(uint32_t*)(Oh + rowB + col) = pack_half(__half2float(hb0), __half2float(hb1));
            *(uint32_t*)(Ol + rowB + col) = pack_half(b0 - __half2float(hb0), b1 - __half2float(hb1));
        }
    }
}

// ============================================================================
// Launch
// ============================================================================
extern "C" void kernel_launch(void* const* d_in, const int* in_sizes, int n_in,
                              void* d_out, int out_size)
{
    const float* X   = (const float*)d_in[0];
    const float* msk = (const float*)d_in[1];
    const int*   pos = (const int*)  d_in[2];
    const float* Wq  = (const float*)d_in[3];
    const float* Wk  = (const float*)d_in[4];
    const float* Wv  = (const float*)d_in[5];
    const float* Wo  = (const float*)d_in[6];
    float* out = (float*)d_out;

    __nv_bfloat16* bf = nullptr;
    cudaGetSymbolAddress((void**)&bf, g_bf16);

    __half*        Xh    = (__half*)(bf + 0 * SLOT);
    __half*        Xl    = (__half*)(bf + 1 * SLOT);
    __half*        Oh16  = (__half*)(bf + 2 * SLOT);
    __half*        Ol16  = (__half*)(bf + 3 * SLOT);
    __half*        WqkvH = (__half*)(bf + 4 * SLOT);
    __half*        WqkvL = (__half*)(bf + 7 * SLOT);
    __half*        Wo16  = (__half*)(bf + 10 * SLOT);
    __nv_bfloat16* Qh    = bf + 12 * SLOT;
    __nv_bfloat16* Ql    = bf + 13 * SLOT;
    __nv_bfloat16* Kh    = bf + 14 * SLOT;
    __nv_bfloat16* Kl    = bf + 15 * SLOT;
    __half*        Vh    = (__half*)(bf + 16 * SLOT);
    __half*        Vl    = (__half*)(bf + 17 * SLOT);

    dim3 sgrid(HIDDEN / 32, HIDDEN / 32, 5);
    split_all_kernel<<<sgrid, 256>>>(X, Wq, Wk, Wv, Wo,
                                     Xh, Xl, WqkvH, WqkvL, Wo16);

    int gsmem = 2 * STAGE_B;     // 81920
    int wsmem = 2 * WO_STAGE;    // 61440
    cudaFuncSetAttribute(gemm_qkv_kernel,
                         cudaFuncAttributeMaxDynamicSharedMemorySize, gsmem);
    cudaFuncSetAttribute(gemm_wo_fp16_kernel,
                         cudaFuncAttributeMaxDynamicSharedMemorySize, wsmem);

    dim3 qkvgrid(3 * HIDDEN / 128, MROWS / 128);   // (96, 32)
    gemm_qkv_kernel<<<qkvgrid, 256, gsmem>>>(Xh, Xl, WqkvH, WqkvL, pos,
                                             Qh, Ql, Kh, Kl, Vh, Vl);

    cudaFuncSetAttribute(attn_mma_kernel,
                         cudaFuncAttributeMaxDynamicSharedMemorySize, A_SMEM_TOTAL);
    dim3 agrid(SEQ / AQ, NHEADS, BATCH);
    attn_mma_kernel<<<agrid, 256, A_SMEM_TOTAL>>>(Qh, Ql, Kh, Kl, Vh, Vl, msk,
                                                  Oh16, Ol16);

    dim3 ogrid(HIDDEN / 128, MROWS / 128);   // (32, 32)
    gemm_wo_fp16_kernel<<<ogrid, 256, wsmem>>>(Oh16, Ol16, Wo16, out);
}

// round 16
// speedup vs baseline: 1.1176x; 1.1176x over previous
#include <cuda_runtime.h>
#include <cuda_bf16.h>
#include <cuda_fp16.h>
#include <math.h>
#include <stdint.h>

#define HIDDEN 4096
#define NHEADS 16
#define HDIM   256
#define ROT    64
#define BATCH  2
#define SEQ    2048
#define MROWS  (BATCH*SEQ)   /* 4096 */

// scratch slots (each 4096*4096 16-bit = 32 MB)
// 0:Xh(fp16) 1:Xl(fp16) 2:O(fp16 single) 3:unused
// 4-6:WqkvH(fp16) 7-9:WqkvL(fp16) 10:Wo(fp16) 11:unused
// 12:Qh 13:Ql 14:Kh 15:Kl (bf16)  16:Vh 17:Vl (fp16)
__device__ __nv_bfloat16 g_bf16[18ull * MROWS * HIDDEN];

#define SLOT ((size_t)MROWS * HIDDEN)

// inv_freq[j] = 10000^(-j/32) = 10^(-j/8), j = 0..31
__constant__ double d_invfreq[32] = {
    1.0,                    0.7498942093324559,    0.5623413251903491,
    0.42169650342858224,    0.31622776601683794,   0.23713737056616552,
    0.17782794100389228,    0.13335214321633242,   0.1,
    0.07498942093324558,    0.05623413251903491,   0.042169650342858224,
    0.03162277660168379,    0.023713737056616554,  0.017782794100389228,
    0.01333521432163324,    0.01,                  0.007498942093324559,
    0.005623413251903491,   0.004216965034285822,  0.0031622776601683794,
    0.0023713737056616554,  0.0017782794100389228, 0.0013335214321633241,
    0.001,                  0.0007498942093324558, 0.0005623413251903491,
    0.00042169650342858227, 0.00031622776601683794,0.00023713737056616552,
    0.00017782794100389227, 0.00013335214321633242
};

// ============================================================================
// PTX helpers
// ============================================================================
__device__ __forceinline__ uint32_t smem_u32(const void* p) {
    uint32_t a;
    asm("{ .reg .u64 t; cvta.to.shared.u64 t, %1; cvt.u32.u64 %0, t; }"
        : "=r"(a) : "l"(p));
    return a;
}

__device__ __forceinline__ void cp_async16(uint32_t dst, const void* src) {
    asm volatile("cp.async.cg.shared.global [%0], [%1], 16;"
                 :: "r"(dst), "l"(src));
}
#define CP_COMMIT() asm volatile("cp.async.commit_group;" ::: "memory")
#define CP_WAIT(n)  asm volatile("cp.async.wait_group %0;" :: "n"(n) : "memory")

__device__ __forceinline__ void ldsm_x4(uint32_t& r0, uint32_t& r1,
                                        uint32_t& r2, uint32_t& r3,
                                        uint32_t addr) {
    asm volatile("ldmatrix.sync.aligned.m8n8.x4.shared.b16 {%0,%1,%2,%3}, [%4];"
                 : "=r"(r0), "=r"(r1), "=r"(r2), "=r"(r3) : "r"(addr));
}
__device__ __forceinline__ void ldsm_x4_t(uint32_t& r0, uint32_t& r1,
                                          uint32_t& r2, uint32_t& r3,
                                          uint32_t addr) {
    asm volatile("ldmatrix.sync.aligned.m8n8.x4.trans.shared.b16 {%0,%1,%2,%3}, [%4];"
                 : "=r"(r0), "=r"(r1), "=r"(r2), "=r"(r3) : "r"(addr));
}

__device__ __forceinline__ void mma_bf16(float c[4],
                                         uint32_t a0, uint32_t a1,
                                         uint32_t a2, uint32_t a3,
                                         uint32_t b0, uint32_t b1) {
    asm volatile(
        "mma.sync.aligned.m16n8k16.row.col.f32.bf16.bf16.f32 "
        "{%0,%1,%2,%3}, {%4,%5,%6,%7}, {%8,%9}, {%0,%1,%2,%3};"
        : "+f"(c[0]), "+f"(c[1]), "+f"(c[2]), "+f"(c[3])
        : "r"(a0), "r"(a1), "r"(a2), "r"(a3), "r"(b0), "r"(b1));
}

__device__ __forceinline__ void mma_fp16(float c[4],
                                         uint32_t a0, uint32_t a1,
                                         uint32_t a2, uint32_t a3,
                                         uint32_t b0, uint32_t b1) {
    asm volatile(
        "mma.sync.aligned.m16n8k16.row.col.f32.f16.f16.f32 "
        "{%0,%1,%2,%3}, {%4,%5,%6,%7}, {%8,%9}, {%0,%1,%2,%3};"
        : "+f"(c[0]), "+f"(c[1]), "+f"(c[2]), "+f"(c[3])
        : "r"(a0), "r"(a1), "r"(a2), "r"(a3), "r"(b0), "r"(b1));
}

__device__ __forceinline__ uint32_t pack_bf16(float a, float b) {
    __nv_bfloat162 t = __floats2bfloat162_rn(a, b);
    return *(uint32_t*)&t;
}
__device__ __forceinline__ uint32_t pack_half(float a, float b) {
    __half2 t = __floats2half2_rn(a, b);
    return *(uint32_t*)&t;
}

// ============================================================================
// Fused split kernel: z=0..2 -> Wq/Wk/Wv transpose+split(fp16 hi/lo),
// z=3 -> Wo transpose+round(fp16 single), z=4 -> X row split(fp16 hi/lo).
// ============================================================================
__global__ __launch_bounds__(256) void split_all_kernel(
    const float* __restrict__ X,
    const float* __restrict__ Wq, const float* __restrict__ Wk,
    const float* __restrict__ Wv, const float* __restrict__ Wo,
    __half* __restrict__ Xh, __half* __restrict__ Xl,
    __half* __restrict__ WqkvH, __half* __restrict__ WqkvL,
    __half* __restrict__ Wo16)
{
    const int z = blockIdx.z;
    if (z == 4) {
        size_t blk = (size_t)blockIdx.y * 128 + blockIdx.x;
        size_t i = (blk * 256 + threadIdx.x) * 4;
        float4 v = *(const float4*)(X + i);
        float f[4] = {v.x, v.y, v.z, v.w};
        __half hh[4], ll[4];
        #pragma unroll
        for (int j = 0; j < 4; j++) {
            hh[j] = __float2half_rn(f[j]);
            ll[j] = __float2half_rn(f[j] - __half2float(hh[j]));
        }
        *(uint2*)(Xh + i) = *(uint2*)hh;
        *(uint2*)(Xl + i) = *(uint2*)ll;
        return;
    }

    __shared__ float t[32][33];
    const float* W;
    __half *H = nullptr, *L = nullptr;
    if (z == 0)      { W = Wq; H = WqkvH;                         L = WqkvL; }
    else if (z == 1) { W = Wk; H = WqkvH + (size_t)4096 * HIDDEN; L = WqkvL + (size_t)4096 * HIDDEN; }
    else if (z == 2) { W = Wv; H = WqkvH + (size_t)8192 * HIDDEN; L = WqkvL + (size_t)8192 * HIDDEN; }
    else             { W = Wo; }

    const int n0 = blockIdx.x * 32;
    const int k0 = blockIdx.y * 32;
    const int tx = threadIdx.x & 31;
    const int ty = threadIdx.x >> 5;
    #pragma unroll
    for (int j = ty; j < 32; j += 8)
        t[j][tx] = W[(size_t)(k0 + j) * HIDDEN + n0 + tx];
    __syncthreads();
    #pragma unroll
    for (int j = ty; j < 32; j += 8) {
        float x = t[tx][j];
        size_t off = (size_t)(n0 + j) * HIDDEN + k0 + tx;
        if (z == 3) {
            Wo16[off] = __float2half_rn(x);
        } else {
            __half h = __float2half_rn(x);
            __half l = __float2half_rn(x - __half2float(h));
            H[off] = h;
            L[off] = l;
        }
    }
}

// ============================================================================
// QKV GEMM, fp16: 3-term for Q/K regions, 2-term for V with Bl loads AND
// ldsm fully skipped (load traffic is the binding constraint, not MMAs).
// CTA 128x128, BK=32, 8 warps 64x32, 2 CTA/SM, single barrier per iter.
// ============================================================================
#define GBK     32
#define TILE_B  10240
#define STAGE_B (4 * TILE_B)

__global__ __launch_bounds__(256, 2) void gemm_qkv_kernel(
    const __half* __restrict__ Ah, const __half* __restrict__ Al,
    const __half* __restrict__ Bh, const __half* __restrict__ Bl,
    const int* __restrict__ pos_ids,
    __nv_bfloat16* __restrict__ Qh, __nv_bfloat16* __restrict__ Ql,
    __nv_bfloat16* __restrict__ Kh, __nv_bfloat16* __restrict__ Kl,
    __half* __restrict__ Vh, __half* __restrict__ Vl)
{
    extern __shared__ char smg[];
    const uint32_t sb = smem_u32(smg);
    const int tid  = threadIdx.x;
    const int wid  = tid >> 5;
    const int lane = tid & 31;
    const int wm = wid >> 2;
    const int wn = wid & 3;
    const int rowbase = blockIdx.y * 128;
    const int colbase = blockIdx.x * 128;
    const int region = colbase >> 12;          // 0=Q, 1=K, 2=V
    const bool term3 = (region < 2);           // V region: 2-term, no Bl
    const int nld = term3 ? 8 : 6;             // V region: skip Bl cp.async

    const __half* bases[4];
    bases[0] = Ah + (size_t)rowbase * HIDDEN;
    bases[1] = Al + (size_t)rowbase * HIDDEN;
    bases[2] = Bh + (size_t)colbase * HIDDEN;
    bases[3] = Bl + (size_t)colbase * HIDDEN;

    const int arow = lane & 15;
    const int aoff = ((lane >> 4) & 1) * 16;
    const int brow = (lane & 7) + ((lane >> 4) & 1) * 8;
    const int boff = ((lane >> 3) & 1) * 16;

    float acc[4][4][4];
    #pragma unroll
    for (int i = 0; i < 4; i++)
        #pragma unroll
        for (int j = 0; j < 4; j++)
            #pragma unroll
            for (int q = 0; q < 4; q++) acc[i][j][q] = 0.0f;

    const int NCH = HIDDEN / GBK;
    {
        #pragma unroll
        for (int it = 0; it < 8; it++) {
            if (it >= nld) break;
            int t = tid + it * 256;
            int tile = t >> 9;
            int r    = (t >> 2) & 127;
            int ch   = t & 3;
            const void* gp = bases[tile] + (size_t)r * HIDDEN + ch * 8;
            uint32_t d = sb + tile * TILE_B + r * 80 + ch * 16;
            cp_async16(d, gp);
        }
        CP_COMMIT();
    }
    for (int c = 0; c < NCH; c++) {
        const int p = c & 1;
        CP_WAIT(0);
        __syncthreads();
        if (c + 1 < NCH) {
            const int kb = (c + 1) * GBK;
            #pragma unroll
            for (int it = 0; it < 8; it++) {
                if (it >= nld) break;
                int t = tid + it * 256;
                int tile = t >> 9;
                int r    = (t >> 2) & 127;
                int ch   = t & 3;
                const void* gp = bases[tile] + (size_t)r * HIDDEN + kb + ch * 8;
                uint32_t d = sb + (p ^ 1) * STAGE_B + tile * TILE_B + r * 80 + ch * 16;
                cp_async16(d, gp);
            }
            CP_COMMIT();
        }
        const uint32_t At_h = sb + p * STAGE_B;
        const uint32_t At_l = At_h + TILE_B;
        const uint32_t Bt_h = At_h + 2 * TILE_B;
        const uint32_t Bt_l = At_h + 3 * TILE_B;
        #pragma unroll
        for (int ks = 0; ks < 2; ks++) {
            const int kbyte = ks * 32;
            uint32_t ah[4][4], al[4][4];
            #pragma unroll
            for (int mi = 0; mi < 4; mi++) {
                ldsm_x4(ah[mi][0], ah[mi][1], ah[mi][2], ah[mi][3],
                        At_h + (wm * 64 + mi * 16 + arow) * 80 + kbyte + aoff);
                ldsm_x4(al[mi][0], al[mi][1], al[mi][2], al[mi][3],
                        At_l + (wm * 64 + mi * 16 + arow) * 80 + kbyte + aoff);
            }
            uint32_t bh[4][2], bl[4][2];
            #pragma unroll
            for (int nf2 = 0; nf2 < 2; nf2++) {
                uint32_t r0, r1, r2, r3;
                ldsm_x4(r0, r1, r2, r3,
                        Bt_h + (wn * 32 + nf2 * 16 + brow) * 80 + kbyte + boff);
                bh[nf2 * 2][0] = r0; bh[nf2 * 2][1] = r1;
                bh[nf2 * 2 + 1][0] = r2; bh[nf2 * 2 + 1][1] = r3;
            }
            if (term3) {
                #pragma unroll
                for (int nf2 = 0; nf2 < 2; nf2++) {
                    uint32_t r0, r1, r2, r3;
                    ldsm_x4(r0, r1, r2, r3,
                            Bt_l + (wn * 32 + nf2 * 16 + brow) * 80 + kbyte + boff);
                    bl[nf2 * 2][0] = r0; bl[nf2 * 2][1] = r1;
                    bl[nf2 * 2 + 1][0] = r2; bl[nf2 * 2 + 1][1] = r3;
                }
            }
            #pragma unroll
            for (int mi = 0; mi < 4; mi++)
                #pragma unroll
                for (int nf = 0; nf < 4; nf++) {
                    mma_fp16(acc[mi][nf], ah[mi][0], ah[mi][1], ah[mi][2], ah[mi][3], bh[nf][0], bh[nf][1]);
                    mma_fp16(acc[mi][nf], al[mi][0], al[mi][1], al[mi][2], al[mi][3], bh[nf][0], bh[nf][1]);
                    if (term3)
                        mma_fp16(acc[mi][nf], ah[mi][0], ah[mi][1], ah[mi][2], ah[mi][3], bl[nf][0], bl[nf][1]);
                }
        }
    }

    const int ncolbase = colbase & 4095;
    const int g = lane >> 2;
    const int t4 = lane & 3;
    const bool rotwarp = (region < 2) && ((colbase & 255) == 0) && (wn < 2);

    double invd[4];
    if (rotwarp) {
        #pragma unroll
        for (int nf = 0; nf < 4; nf++)
            invd[nf] = d_invfreq[wn * 16 + nf * 4 + t4];
    }
    const float qscale = (region == 0) ? 0.0625f : 1.0f;
    __nv_bfloat16 *H = (region == 0) ? Qh : Kh;
    __nv_bfloat16 *L = (region == 0) ? Ql : Kl;

    #pragma unroll
    for (int mi = 0; mi < 4; mi++) {
        const int rA = rowbase + wm * 64 + mi * 16 + g;
        const int rB = rA + 8;
        int posA = 0, posB = 0;
        if (rotwarp) { posA = pos_ids[rA]; posB = pos_ids[rB]; }
        #pragma unroll
        for (int nf = 0; nf < 4; nf++) {
            float v0 = acc[mi][nf][0], v1 = acc[mi][nf][1];
            float v2 = acc[mi][nf][2], v3 = acc[mi][nf][3];
            if (rotwarp) {
                float angA = (float)((double)posA * invd[nf]);
                float angB = (float)((double)posB * invd[nf]);
                float sA = sinf(angA), cA = cosf(angA);
                float sB = sinf(angB), cB = cosf(angB);
                float t0 = v0 * cA - v1 * sA;
                float t1 = v1 * cA + v0 * sA;
                v0 = t0; v1 = t1;
                t0 = v2 * cB - v3 * sB;
                t1 = v3 * cB + v2 * sB;
                v2 = t0; v3 = t1;
            }
            v0 *= qscale; v1 *= qscale; v2 *= qscale; v3 *= qscale;

            size_t ncol = (size_t)(ncolbase + wn * 32 + nf * 8 + t4 * 2);
            size_t offA = (size_t)rA * HIDDEN + ncol;
            size_t offB = (size_t)rB * HIDDEN + ncol;

            if (region == 2) {
                __half h0 = __float2half_rn(v0), h1 = __float2half_rn(v1);
                __half h2 = __float2half_rn(v2), h3 = __float2half_rn(v3);
                float l0 = v0 - __half2float(h0), l1 = v1 - __half2float(h1);
                float l2 = v2 - __half2float(h2), l3 = v3 - __half2float(h3);
                *(uint32_t*)(Vh + offA) = pack_half(__half2float(h0), __half2float(h1));
                *(uint32_t*)(Vl + offA) = pack_half(l0, l1);
                *(uint32_t*)(Vh + offB) = pack_half(__half2float(h2), __half2float(h3));
                *(uint32_t*)(Vl + offB) = pack_half(l2, l3);
            } else {
                __nv_bfloat16 h0 = __float2bfloat16(v0), h1 = __float2bfloat16(v1);
                __nv_bfloat16 h2 = __float2bfloat16(v2), h3 = __float2bfloat16(v3);
                float l0 = v0 - __bfloat162float(h0), l1 = v1 - __bfloat162float(h1);
                float l2 = v2 - __bfloat162float(h2), l3 = v3 - __bfloat162float(h3);
                *(uint32_t*)(H + offA) = pack_bf16(__bfloat162float(h0), __bfloat162float(h1));
                *(uint32_t*)(L + offA) = pack_bf16(l0, l1);
                *(uint32_t*)(H + offB) = pack_bf16(__bfloat162float(h2), __bfloat162float(h3));
                *(uint32_t*)(L + offB) = pack_bf16(l2, l3);
            }
        }
    }
}

// ============================================================================
// Wo GEMM, fp16 single-term: C = fp16(O) @ fp16(Wo)^T.
// 2 smem tiles per stage, 1 MMA per fragment pair. Last stage -> unamplified.
// ============================================================================
#define WO_STAGE (2 * TILE_B)   /* 20480 */

__global__ __launch_bounds__(256, 2) void gemm_wo_fp16_kernel(
    const __half* __restrict__ Ah,
    const __half* __restrict__ Bh, float* __restrict__ C)
{
    extern __shared__ char smg[];
    const uint32_t sb = smem_u32(smg);
    const int tid  = threadIdx.x;
    const int wid  = tid >> 5;
    const int lane = tid & 31;
    const int wm = wid >> 2;
    const int wn = wid & 3;
    const int rowbase = blockIdx.y * 128;
    const int colbase = blockIdx.x * 128;

    const __half* bases[2];
    bases[0] = Ah + (size_t)rowbase * HIDDEN;
    bases[1] = Bh + (size_t)colbase * HIDDEN;

    const int arow = lane & 15;
    const int aoff = ((lane >> 4) & 1) * 16;
    const int brow = (lane & 7) + ((lane >> 4) & 1) * 8;
    const int boff = ((lane >> 3) & 1) * 16;

    float acc[4][4][4];
    #pragma unroll
    for (int i = 0; i < 4; i++)
        #pragma unroll
        for (int j = 0; j < 4; j++)
            #pragma unroll
            for (int q = 0; q < 4; q++) acc[i][j][q] = 0.0f;

    const int NCH = HIDDEN / GBK;
    {
        #pragma unroll
        for (int it = 0; it < 4; it++) {
            int t = tid + it * 256;          // 0..1023
            int tile = t >> 9;               // 0..1
            int r    = (t >> 2) & 127;
            int ch   = t & 3;
            const void* gp = bases[tile] + (size_t)r * HIDDEN + ch * 8;
            uint32_t d = sb + tile * TILE_B + r * 80 + ch * 16;
            cp_async16(d, gp);
        }
        CP_COMMIT();
    }
    for (int c = 0; c < NCH; c++) {
        const int p = c & 1;
        CP_WAIT(0);
        __syncthreads();
        if (c + 1 < NCH) {
            const int kb = (c + 1) * GBK;
            #pragma unroll
            for (int it = 0; it < 4; it++) {
                int t = tid + it * 256;
                int tile = t >> 9;
                int r    = (t >> 2) & 127;
                int ch   = t & 3;
                const void* gp = bases[tile] + (size_t)r * HIDDEN + kb + ch * 8;
                uint32_t d = sb + (p ^ 1) * WO_STAGE + tile * TILE_B + r * 80 + ch * 16;
                cp_async16(d, gp);
            }
            CP_COMMIT();
        }
        const uint32_t At_h = sb + p * WO_STAGE;
        const uint32_t Bt_h = At_h + TILE_B;
        #pragma unroll
        for (int ks = 0; ks < 2; ks++) {
            const int kbyte = ks * 32;
            uint32_t ah[4][4];
            #pragma unroll
            for (int mi = 0; mi < 4; mi++) {
                ldsm_x4(ah[mi][0], ah[mi][1], ah[mi][2], ah[mi][3],
                        At_h + (wm * 64 + mi * 16 + arow) * 80 + kbyte + aoff);
            }
            uint32_t bh[4][2];
            #pragma unroll
            for (int nf2 = 0; nf2 < 2; nf2++) {
                uint32_t r0, r1, r2, r3;
                ldsm_x4(r0, r1, r2, r3,
                        Bt_h + (wn * 32 + nf2 * 16 + brow) * 80 + kbyte + boff);
                bh[nf2 * 2][0] = r0; bh[nf2 * 2][1] = r1;
                bh[nf2 * 2 + 1][0] = r2; bh[nf2 * 2 + 1][1] = r3;
            }
            #pragma unroll
            for (int mi = 0; mi < 4; mi++)
                #pragma unroll
                for (int nf = 0; nf < 4; nf++)
                    mma_fp16(acc[mi][nf], ah[mi][0], ah[mi][1], ah[mi][2], ah[mi][3], bh[nf][0], bh[nf][1]);
        }
    }

    const int g = lane >> 2;
    const int t = lane & 3;
    #pragma unroll
    for (int mi = 0; mi < 4; mi++) {
        #pragma unroll
        for (int nf = 0; nf < 4; nf++) {
            float* base = C + (size_t)(rowbase + wm * 64 + mi * 16 + g) * HIDDEN
                            + colbase + wn * 32 + nf * 8 + t * 2;
            *(float2*)base = make_float2(acc[mi][nf][0], acc[mi][nf][1]);
            *(float2*)(base + (size_t)8 * HIDDEN) = make_float2(acc[mi][nf][2], acc[mi][nf][3]);
        }
    }
}

// ============================================================================
// Flash attention: QK bf16x3 (amplified path, full precision);
// P fp16-single; V fp16 hi/lo; O written as fp16-single.
// ============================================================================
#define AQ   64
#define AKV  64
#define QSTR 528
#define PSTR 144

#define A_QH 0
#define A_QL 33792
#define A_KH 67584
#define A_KL 101376
#define A_VH 135168
#define A_VL 168960
#define A_PH 202752
#define A_ST 221184
#define A_SMEM_TOTAL 223488

__global__ __launch_bounds__(256, 1) void attn_mma_kernel(
    const __nv_bfloat16* __restrict__ Qh_g, const __nv_bfloat16* __restrict__ Ql_g,
    const __nv_bfloat16* __restrict__ Kh_g, const __nv_bfloat16* __restrict__ Kl_g,
    const __half* __restrict__ Vh_g, const __half* __restrict__ Vl_g,
    const float* __restrict__ amask,
    __half* __restrict__ Oh)
{
    extern __shared__ char sma[];
    const uint32_t sb = smem_u32(sma);
    float* pmax   = (float*)(sma + A_ST);
    float* psum   = (float*)(sma + A_ST + 512);
    float* mrow   = (float*)(sma + A_ST + 1024);
    float* lrow   = (float*)(sma + A_ST + 1280);
    float* corr   = (float*)(sma + A_ST + 1536);
    float* mnew   = (float*)(sma + A_ST + 1792);
    float* amask_s= (float*)(sma + A_ST + 2048);

    const int tid  = threadIdx.x;
    const int wid  = tid >> 5;
    const int lane = tid & 31;
    const int qg   = wid & 3;
    const int kvh  = wid >> 2;
    const int dh   = wid >> 2;
    const int qt   = (int)gridDim.x - 1 - (int)blockIdx.x;
    const int h    = blockIdx.y;
    const int b    = blockIdx.z;
    const int q0   = qt * AQ;

    const int g = lane >> 2;
    const int t4 = lane & 3;
    const int arow = lane & 15;
    const int aoff = ((lane >> 4) & 1) * 16;
    const int brow = (lane & 7) + ((lane >> 4) & 1) * 8;
    const int boff = ((lane >> 3) & 1) * 16;
    const int vrow = (lane & 7) + ((lane >> 3) & 1) * 8;
    const int vcoff = (lane >> 4) * 8;

    if (tid < 64) { mrow[tid] = -1e30f; lrow[tid] = 0.0f; }

    {
        const __nv_bfloat16* qh = Qh_g + (size_t)(b * SEQ + q0) * HIDDEN + h * 256;
        const __nv_bfloat16* ql = Ql_g + (size_t)(b * SEQ + q0) * HIDDEN + h * 256;
        #pragma unroll
        for (int it = 0; it < 8; it++) {
            int t = tid + it * 256;
            int r = t >> 5, c = t & 31;
            cp_async16(sb + A_QH + r * QSTR + c * 16, qh + (size_t)r * HIDDEN + c * 8);
            cp_async16(sb + A_QL + r * QSTR + c * 16, ql + (size_t)r * HIDDEN + c * 8);
        }
    }

    float o[16][4];
    #pragma unroll
    for (int i = 0; i < 16; i++)
        #pragma unroll
        for (int q = 0; q < 4; q++) o[i][q] = 0.0f;

    for (int kc = 0; kc <= qt; kc++) {
        const int k0 = kc * AKV;
        if (kc) __syncthreads();

        {
            const __nv_bfloat16* kh = Kh_g + (size_t)(b * SEQ + k0) * HIDDEN + h * 256;
            const __nv_bfloat16* kl = Kl_g + (size_t)(b * SEQ + k0) * HIDDEN + h * 256;
            #pragma unroll
            for (int it = 0; it < 8; it++) {
                int t = tid + it * 256;
                int r = t >> 5, c = t & 31;
                cp_async16(sb + A_KH + r * QSTR + c * 16, kh + (size_t)r * HIDDEN + c * 8);
                cp_async16(sb + A_KL + r * QSTR + c * 16, kl + (size_t)r * HIDDEN + c * 8);
            }
            CP_COMMIT();
        }
        {
            const __half* vh = Vh_g + (size_t)(b * SEQ + k0) * HIDDEN + h * 256;
            const __half* vl = Vl_g + (size_t)(b * SEQ + k0) * HIDDEN + h * 256;
            #pragma unroll
            for (int it = 0; it < 8; it++) {
                int t = tid + it * 256;
                int r = t >> 5, c = t & 31;
                cp_async16(sb + A_VH + r * QSTR + c * 16, vh + (size_t)r * HIDDEN + c * 8);
                cp_async16(sb + A_VL + r * QSTR + c * 16, vl + (size_t)r * HIDDEN + c * 8);
            }
            CP_COMMIT();
        }
        if (tid < 64) amask_s[tid] = amask[b * SEQ + k0 + tid];

        CP_WAIT(1);
        __syncthreads();

        float s[4][4];
        #pragma unroll
        for (int nt = 0; nt < 4; nt++)
            #pragma unroll
            for (int q = 0; q < 4; q++) s[nt][q] = 0.0f;

        #pragma unroll
        for (int ks = 0; ks < 16; ks++) {
            const int kb = ks * 32;
            uint32_t qah[4], qal[4];
            ldsm_x4(qah[0], qah[1], qah[2], qah[3],
                    sb + A_QH + (qg * 16 + arow) * QSTR + kb + aoff);
            ldsm_x4(qal[0], qal[1], qal[2], qal[3],
                    sb + A_QL + (qg * 16 + arow) * QSTR + kb + aoff);
            uint32_t kbh[4][2], kbl[4][2];
            #pragma unroll
            for (int n2 = 0; n2 < 2; n2++) {
                uint32_t r0, r1, r2, r3;
                ldsm_x4(r0, r1, r2, r3,
                        sb + A_KH + (kvh * 32 + n2 * 16 + brow) * QSTR + kb + boff);
                kbh[n2 * 2][0] = r0; kbh[n2 * 2][1] = r1;
                kbh[n2 * 2 + 1][0] = r2; kbh[n2 * 2 + 1][1] = r3;
                ldsm_x4(r0, r1, r2, r3,
                        sb + A_KL + (kvh * 32 + n2 * 16 + brow) * QSTR + kb + boff);
                kbl[n2 * 2][0] = r0; kbl[n2 * 2][1] = r1;
                kbl[n2 * 2 + 1][0] = r2; kbl[n2 * 2 + 1][1] = r3;
            }
            #pragma unroll
            for (int nt = 0; nt < 4; nt++) {
                mma_bf16(s[nt], qah[0], qah[1], qah[2], qah[3], kbh[nt][0], kbh[nt][1]);
                mma_bf16(s[nt], qah[0], qah[1], qah[2], qah[3], kbl[nt][0], kbl[nt][1]);
                mma_bf16(s[nt], qal[0], qal[1], qal[2], qal[3], kbh[nt][0], kbh[nt][1]);
            }
        }

        const int rA = q0 + qg * 16 + g;
        const int rB = rA + 8;
        #pragma unroll
        for (int nt = 0; nt < 4; nt++) {
            int lc = kvh * 32 + nt * 8 + t4 * 2;
            int cg = k0 + lc;
            bool p0 = amask_s[lc] > 0.0f;
            bool p1 = amask_s[lc + 1] > 0.0f;
            if (cg > rA || !p0)     s[nt][0] = -1e30f;
            if (cg + 1 > rA || !p1) s[nt][1] = -1e30f;
            if (cg > rB || !p0)     s[nt][2] = -1e30f;
            if (cg + 1 > rB || !p1) s[nt][3] = -1e30f;
        }

        float mA = -1e30f, mB = -1e30f;
        #pragma unroll
        for (int nt = 0; nt < 4; nt++) {
            mA = fmaxf(mA, fmaxf(s[nt][0], s[nt][1]));
            mB = fmaxf(mB, fmaxf(s[nt][2], s[nt][3]));
        }
        mA = fmaxf(mA, __shfl_xor_sync(0xffffffffu, mA, 1));
        mA = fmaxf(mA, __shfl_xor_sync(0xffffffffu, mA, 2));
        mB = fmaxf(mB, __shfl_xor_sync(0xffffffffu, mB, 1));
        mB = fmaxf(mB, __shfl_xor_sync(0xffffffffu, mB, 2));
        if (t4 == 0) {
            pmax[kvh * 64 + qg * 16 + g] = mA;
            pmax[kvh * 64 + qg * 16 + g + 8] = mB;
        }
        __syncthreads();

        if (tid < 64) {
            float mo = mrow[tid];
            float pm = fmaxf(pmax[tid], pmax[64 + tid]);
            float mn = fmaxf(mo, pm);
            mnew[tid] = mn;
            corr[tid] = __expf(mo - mn);
            mrow[tid] = mn;
        }
        __syncthreads();

        {
            float mnA = mnew[qg * 16 + g];
            float mnB = mnew[qg * 16 + g + 8];
            float sA = 0.0f, sB = 0.0f;
            #pragma unroll
            for (int nt = 0; nt < 4; nt++) {
                float p0 = __expf(s[nt][0] - mnA);
                float p1 = __expf(s[nt][1] - mnA);
                float p2 = __expf(s[nt][2] - mnB);
                float p3 = __expf(s[nt][3] - mnB);
                sA += p0 + p1;
                sB += p2 + p3;
                uint32_t cb = (kvh * 32 + nt * 8 + t4 * 2) * 2;
                uint32_t adrA = (qg * 16 + g) * PSTR + cb;
                uint32_t adrB = (qg * 16 + g + 8) * PSTR + cb;
                *(uint32_t*)(sma + A_PH + adrA) = pack_half(p0, p1);
                *(uint32_t*)(sma + A_PH + adrB) = pack_half(p2, p3);
            }
            sA += __shfl_xor_sync(0xffffffffu, sA, 1);
            sA += __shfl_xor_sync(0xffffffffu, sA, 2);
            sB += __shfl_xor_sync(0xffffffffu, sB, 1);
            sB += __shfl_xor_sync(0xffffffffu, sB, 2);
            if (t4 == 0) {
                psum[kvh * 64 + qg * 16 + g] = sA;
                psum[kvh * 64 + qg * 16 + g + 8] = sB;
            }
        }
        CP_WAIT(0);
        __syncthreads();

        if (tid < 64)
            lrow[tid] = lrow[tid] * corr[tid] + psum[tid] + psum[64 + tid];

        {
            float cA = corr[qg * 16 + g];
            float cB = corr[qg * 16 + g + 8];
            #pragma unroll
            for (int nt = 0; nt < 16; nt++) {
                o[nt][0] *= cA; o[nt][1] *= cA;
                o[nt][2] *= cB; o[nt][3] *= cB;
            }
        }
        #pragma unroll
        for (int ks = 0; ks < 4; ks++) {
            uint32_t pah[4];
            ldsm_x4(pah[0], pah[1], pah[2], pah[3],
                    sb + A_PH + (qg * 16 + arow) * PSTR + ks * 32 + aoff);
            #pragma unroll
            for (int np = 0; np < 8; np++) {
                int col = dh * 128 + np * 16 + vcoff;
                uint32_t vrowg = (ks * 16 + vrow) * QSTR + col * 2;
                uint32_t vh0, vh1, vh2, vh3, vl0, vl1, vl2, vl3;
                ldsm_x4_t(vh0, vh1, vh2, vh3, sb + A_VH + vrowg);
                ldsm_x4_t(vl0, vl1, vl2, vl3, sb + A_VL + vrowg);
                mma_fp16(o[np * 2], pah[0], pah[1], pah[2], pah[3], vh0, vh1);
                mma_fp16(o[np * 2], pah[0], pah[1], pah[2], pah[3], vl0, vl1);
                mma_fp16(o[np * 2 + 1], pah[0], pah[1], pah[2], pah[3], vh2, vh3);
                mma_fp16(o[np * 2 + 1], pah[0], pah[1], pah[2], pah[3], vl2, vl3);
            }
        }
    }

    __syncthreads();
    {
        float invA = 1.0f / lrow[qg * 16 + g];
        float invB = 1.0f / lrow[qg * 16 + g + 8];
        size_t rowA = (size_t)(b * SEQ + q0 + qg * 16 + g) * HIDDEN;
        size_t rowB = rowA + (size_t)8 * HIDDEN;
        int colbase = h * 256 + dh * 128 + t4 * 2;
        #pragma unroll
        for (int nt = 0; nt < 16; nt++) {
            int col = colbase + nt * 8;
            *(uint32_t*)(Oh + rowA + col) = pack_half(o[nt][0] * invA, o[nt][1] * invA);
            *(uint32_t*)(Oh + rowB + col) = pack_half(o[nt][2] * invB, o[nt][3] * invB);
        }
    }
}

// ============================================================================
// Launch
// ============================================================================
extern "C" void kernel_launch(void* const* d_in, const int* in_sizes, int n_in,
                              void* d_out, int out_size)
{
    const float* X   = (const float*)d_in[0];
    const float* msk = (const float*)d_in[1];
    const int*   pos = (const int*)  d_in[2];
    const float* Wq  = (const float*)d_in[3];
    const float* Wk  = (const float*)d_in[4];
    const float* Wv  = (const float*)d_in[5];
    const float* Wo  = (const float*)d_in[6];
    float* out = (float*)d_out;

    __nv_bfloat16* bf = nullptr;
    cudaGetSymbolAddress((void**)&bf, g_bf16);

    __half*        Xh    = (__half*)(bf + 0 * SLOT);
    __half*        Xl    = (__half*)(bf + 1 * SLOT);
    __half*        Oh16  = (__half*)(bf + 2 * SLOT);
    __half*        WqkvH = (__half*)(bf + 4 * SLOT);
    __half*        WqkvL = (__half*)(bf + 7 * SLOT);
    __half*        Wo16  = (__half*)(bf + 10 * SLOT);
    __nv_bfloat16* Qh    = bf + 12 * SLOT;
    __nv_bfloat16* Ql    = bf + 13 * SLOT;
    __nv_bfloat16* Kh    = bf + 14 * SLOT;
    __nv_bfloat16* Kl    = bf + 15 * SLOT;
    __half*        Vh    = (__half*)(bf + 16 * SLOT);
    __half*        Vl    = (__half*)(bf + 17 * SLOT);

    dim3 sgrid(HIDDEN / 32, HIDDEN / 32, 5);
    split_all_kernel<<<sgrid, 256>>>(X, Wq, Wk, Wv, Wo,
                                     Xh, Xl, WqkvH, WqkvL, Wo16);

    int gsmem = 2 * STAGE_B;     // 81920
    int wsmem = 2 * WO_STAGE;    // 40960
    cudaFuncSetAttribute(gemm_qkv_kernel,
                         cudaFuncAttributeMaxDynamicSharedMemorySize, gsmem);
    cudaFuncSetAttribute(gemm_wo_fp16_kernel,
                         cudaFuncAttributeMaxDynamicSharedMemorySize, wsmem);

    dim3 qkvgrid(3 * HIDDEN / 128, MROWS / 128);   // (96, 32)
    gemm_qkv_kernel<<<qkvgrid, 256, gsmem>>>(Xh, Xl, WqkvH, WqkvL, pos,
                                             Qh, Ql, Kh, Kl, Vh, Vl);

    cudaFuncSetAttribute(attn_mma_kernel,
                         cudaFuncAttributeMaxDynamicSharedMemorySize, A_SMEM_TOTAL);
    dim3 agrid(SEQ / AQ, NHEADS, BATCH);
    attn_mma_kernel<<<agrid, 256, A_SMEM_TOTAL>>>(Qh, Ql, Kh, Kl, Vh, Vl, msk,
                                                  Oh16);

    dim3 ogrid(HIDDEN / 128, MROWS / 128);   // (32, 32)
    gemm_wo_fp16_kernel<<<ogrid, 256, wsmem>>>(Oh16, Wo16, out);
}

// round 17
// speedup vs baseline: 1.1427x; 1.0225x over previous
#include <cuda_runtime.h>
#include <cuda_bf16.h>
#include <cuda_fp16.h>
#include <math.h>
#include <stdint.h>

#define HIDDEN 4096
#define NHEADS 16
#define HDIM   256
#define ROT    64
#define BATCH  2
#define SEQ    2048
#define MROWS  (BATCH*SEQ)   /* 4096 */

// scratch slots (each 4096*4096 16-bit = 32 MB)
// 0:Xh 1:Xl 2:O(fp16 single) 3:unused
// 4-6:WqkvH 7-9:WqkvL 10:Wo16 11:unused
// 12:Qh 13:Ql 14:Kh 15:Kl (fp16)  16:V (fp16 single) 17:unused
__device__ __nv_bfloat16 g_bf16[18ull * MROWS * HIDDEN];

#define SLOT ((size_t)MROWS * HIDDEN)

// inv_freq[j] = 10000^(-j/32) = 10^(-j/8), j = 0..31
__constant__ double d_invfreq[32] = {
    1.0,                    0.7498942093324559,    0.5623413251903491,
    0.42169650342858224,    0.31622776601683794,   0.23713737056616552,
    0.17782794100389228,    0.13335214321633242,   0.1,
    0.07498942093324558,    0.05623413251903491,   0.042169650342858224,
    0.03162277660168379,    0.023713737056616554,  0.017782794100389228,
    0.01333521432163324,    0.01,                  0.007498942093324559,
    0.005623413251903491,   0.004216965034285822,  0.0031622776601683794,
    0.0023713737056616554,  0.0017782794100389228, 0.0013335214321633241,
    0.001,                  0.0007498942093324558, 0.0005623413251903491,
    0.00042169650342858227, 0.00031622776601683794,0.00023713737056616552,
    0.00017782794100389227, 0.00013335214321633242
};

// ============================================================================
// PTX helpers
// ============================================================================
__device__ __forceinline__ uint32_t smem_u32(const void* p) {
    uint32_t a;
    asm("{ .reg .u64 t; cvta.to.shared.u64 t, %1; cvt.u32.u64 %0, t; }"
        : "=r"(a) : "l"(p));
    return a;
}

__device__ __forceinline__ void cp_async16(uint32_t dst, const void* src) {
    asm volatile("cp.async.cg.shared.global [%0], [%1], 16;"
                 :: "r"(dst), "l"(src));
}
#define CP_COMMIT() asm volatile("cp.async.commit_group;" ::: "memory")
#define CP_WAIT(n)  asm volatile("cp.async.wait_group %0;" :: "n"(n) : "memory")

__device__ __forceinline__ void ldsm_x4(uint32_t& r0, uint32_t& r1,
                                        uint32_t& r2, uint32_t& r3,
                                        uint32_t addr) {
    asm volatile("ldmatrix.sync.aligned.m8n8.x4.shared.b16 {%0,%1,%2,%3}, [%4];"
                 : "=r"(r0), "=r"(r1), "=r"(r2), "=r"(r3) : "r"(addr));
}
__device__ __forceinline__ void ldsm_x4_t(uint32_t& r0, uint32_t& r1,
                                          uint32_t& r2, uint32_t& r3,
                                          uint32_t addr) {
    asm volatile("ldmatrix.sync.aligned.m8n8.x4.trans.shared.b16 {%0,%1,%2,%3}, [%4];"
                 : "=r"(r0), "=r"(r1), "=r"(r2), "=r"(r3) : "r"(addr));
}

__device__ __forceinline__ void mma_fp16(float c[4],
                                         uint32_t a0, uint32_t a1,
                                         uint32_t a2, uint32_t a3,
                                         uint32_t b0, uint32_t b1) {
    asm volatile(
        "mma.sync.aligned.m16n8k16.row.col.f32.f16.f16.f32 "
        "{%0,%1,%2,%3}, {%4,%5,%6,%7}, {%8,%9}, {%0,%1,%2,%3};"
        : "+f"(c[0]), "+f"(c[1]), "+f"(c[2]), "+f"(c[3])
        : "r"(a0), "r"(a1), "r"(a2), "r"(a3), "r"(b0), "r"(b1));
}

__device__ __forceinline__ uint32_t pack_half(float a, float b) {
    __half2 t = __floats2half2_rn(a, b);
    return *(uint32_t*)&t;
}

// ============================================================================
// Fused split kernel: z=0..2 -> Wq/Wk/Wv transpose+split(fp16 hi/lo),
// z=3 -> Wo transpose+round(fp16 single), z=4 -> X row split(fp16 hi/lo).
// ============================================================================
__global__ __launch_bounds__(256) void split_all_kernel(
    const float* __restrict__ X,
    const float* __restrict__ Wq, const float* __restrict__ Wk,
    const float* __restrict__ Wv, const float* __restrict__ Wo,
    __half* __restrict__ Xh, __half* __restrict__ Xl,
    __half* __restrict__ WqkvH, __half* __restrict__ WqkvL,
    __half* __restrict__ Wo16)
{
    const int z = blockIdx.z;
    if (z == 4) {
        size_t blk = (size_t)blockIdx.y * 128 + blockIdx.x;
        size_t i = (blk * 256 + threadIdx.x) * 4;
        float4 v = *(const float4*)(X + i);
        float f[4] = {v.x, v.y, v.z, v.w};
        __half hh[4], ll[4];
        #pragma unroll
        for (int j = 0; j < 4; j++) {
            hh[j] = __float2half_rn(f[j]);
            ll[j] = __float2half_rn(f[j] - __half2float(hh[j]));
        }
        *(uint2*)(Xh + i) = *(uint2*)hh;
        *(uint2*)(Xl + i) = *(uint2*)ll;
        return;
    }

    __shared__ float t[32][33];
    const float* W;
    __half *H = nullptr, *L = nullptr;
    if (z == 0)      { W = Wq; H = WqkvH;                         L = WqkvL; }
    else if (z == 1) { W = Wk; H = WqkvH + (size_t)4096 * HIDDEN; L = WqkvL + (size_t)4096 * HIDDEN; }
    else if (z == 2) { W = Wv; H = WqkvH + (size_t)8192 * HIDDEN; L = WqkvL + (size_t)8192 * HIDDEN; }
    else             { W = Wo; }

    const int n0 = blockIdx.x * 32;
    const int k0 = blockIdx.y * 32;
    const int tx = threadIdx.x & 31;
    const int ty = threadIdx.x >> 5;
    #pragma unroll
    for (int j = ty; j < 32; j += 8)
        t[j][tx] = W[(size_t)(k0 + j) * HIDDEN + n0 + tx];
    __syncthreads();
    #pragma unroll
    for (int j = ty; j < 32; j += 8) {
        float x = t[tx][j];
        size_t off = (size_t)(n0 + j) * HIDDEN + k0 + tx;
        if (z == 3) {
            Wo16[off] = __float2half_rn(x);
        } else {
            __half h = __float2half_rn(x);
            __half l = __float2half_rn(x - __half2float(h));
            H[off] = h;
            L[off] = l;
        }
    }
}

// ============================================================================
// QKV GEMM, fp16: 3-term for Q/K regions, 2-term for V (Bl skipped entirely).
// Outputs: Q/K as fp16 hi/lo, V as fp16 single.
// CTA 128x128, BK=32, 8 warps 64x32, 2 CTA/SM, single barrier per iter.
// ============================================================================
#define GBK     32
#define TILE_B  10240
#define STAGE_B (4 * TILE_B)

__global__ __launch_bounds__(256, 2) void gemm_qkv_kernel(
    const __half* __restrict__ Ah, const __half* __restrict__ Al,
    const __half* __restrict__ Bh, const __half* __restrict__ Bl,
    const int* __restrict__ pos_ids,
    __half* __restrict__ Qh, __half* __restrict__ Ql,
    __half* __restrict__ Kh, __half* __restrict__ Kl,
    __half* __restrict__ Vh)
{
    extern __shared__ char smg[];
    const uint32_t sb = smem_u32(smg);
    const int tid  = threadIdx.x;
    const int wid  = tid >> 5;
    const int lane = tid & 31;
    const int wm = wid >> 2;
    const int wn = wid & 3;
    const int rowbase = blockIdx.y * 128;
    const int colbase = blockIdx.x * 128;
    const int region = colbase >> 12;          // 0=Q, 1=K, 2=V
    const bool term3 = (region < 2);           // V region: 2-term, no Bl
    const int nld = term3 ? 8 : 6;             // V region: skip Bl cp.async

    const __half* bases[4];
    bases[0] = Ah + (size_t)rowbase * HIDDEN;
    bases[1] = Al + (size_t)rowbase * HIDDEN;
    bases[2] = Bh + (size_t)colbase * HIDDEN;
    bases[3] = Bl + (size_t)colbase * HIDDEN;

    const int arow = lane & 15;
    const int aoff = ((lane >> 4) & 1) * 16;
    const int brow = (lane & 7) + ((lane >> 4) & 1) * 8;
    const int boff = ((lane >> 3) & 1) * 16;

    float acc[4][4][4];
    #pragma unroll
    for (int i = 0; i < 4; i++)
        #pragma unroll
        for (int j = 0; j < 4; j++)
            #pragma unroll
            for (int q = 0; q < 4; q++) acc[i][j][q] = 0.0f;

    const int NCH = HIDDEN / GBK;
    {
        #pragma unroll
        for (int it = 0; it < 8; it++) {
            if (it >= nld) break;
            int t = tid + it * 256;
            int tile = t >> 9;
            int r    = (t >> 2) & 127;
            int ch   = t & 3;
            const void* gp = bases[tile] + (size_t)r * HIDDEN + ch * 8;
            uint32_t d = sb + tile * TILE_B + r * 80 + ch * 16;
            cp_async16(d, gp);
        }
        CP_COMMIT();
    }
    for (int c = 0; c < NCH; c++) {
        const int p = c & 1;
        CP_WAIT(0);
        __syncthreads();
        if (c + 1 < NCH) {
            const int kb = (c + 1) * GBK;
            #pragma unroll
            for (int it = 0; it < 8; it++) {
                if (it >= nld) break;
                int t = tid + it * 256;
                int tile = t >> 9;
                int r    = (t >> 2) & 127;
                int ch   = t & 3;
                const void* gp = bases[tile] + (size_t)r * HIDDEN + kb + ch * 8;
                uint32_t d = sb + (p ^ 1) * STAGE_B + tile * TILE_B + r * 80 + ch * 16;
                cp_async16(d, gp);
            }
            CP_COMMIT();
        }
        const uint32_t At_h = sb + p * STAGE_B;
        const uint32_t At_l = At_h + TILE_B;
        const uint32_t Bt_h = At_h + 2 * TILE_B;
        const uint32_t Bt_l = At_h + 3 * TILE_B;
        #pragma unroll
        for (int ks = 0; ks < 2; ks++) {
            const int kbyte = ks * 32;
            uint32_t ah[4][4], al[4][4];
            #pragma unroll
            for (int mi = 0; mi < 4; mi++) {
                ldsm_x4(ah[mi][0], ah[mi][1], ah[mi][2], ah[mi][3],
                        At_h + (wm * 64 + mi * 16 + arow) * 80 + kbyte + aoff);
                ldsm_x4(al[mi][0], al[mi][1], al[mi][2], al[mi][3],
                        At_l + (wm * 64 + mi * 16 + arow) * 80 + kbyte + aoff);
            }
            uint32_t bh[4][2], bl[4][2];
            #pragma unroll
            for (int nf2 = 0; nf2 < 2; nf2++) {
                uint32_t r0, r1, r2, r3;
                ldsm_x4(r0, r1, r2, r3,
                        Bt_h + (wn * 32 + nf2 * 16 + brow) * 80 + kbyte + boff);
                bh[nf2 * 2][0] = r0; bh[nf2 * 2][1] = r1;
                bh[nf2 * 2 + 1][0] = r2; bh[nf2 * 2 + 1][1] = r3;
            }
            if (term3) {
                #pragma unroll
                for (int nf2 = 0; nf2 < 2; nf2++) {
                    uint32_t r0, r1, r2, r3;
                    ldsm_x4(r0, r1, r2, r3,
                            Bt_l + (wn * 32 + nf2 * 16 + brow) * 80 + kbyte + boff);
                    bl[nf2 * 2][0] = r0; bl[nf2 * 2][1] = r1;
                    bl[nf2 * 2 + 1][0] = r2; bl[nf2 * 2 + 1][1] = r3;
                }
            }
            #pragma unroll
            for (int mi = 0; mi < 4; mi++)
                #pragma unroll
                for (int nf = 0; nf < 4; nf++) {
                    mma_fp16(acc[mi][nf], ah[mi][0], ah[mi][1], ah[mi][2], ah[mi][3], bh[nf][0], bh[nf][1]);
                    mma_fp16(acc[mi][nf], al[mi][0], al[mi][1], al[mi][2], al[mi][3], bh[nf][0], bh[nf][1]);
                    if (term3)
                        mma_fp16(acc[mi][nf], ah[mi][0], ah[mi][1], ah[mi][2], ah[mi][3], bl[nf][0], bl[nf][1]);
                }
        }
    }

    const int ncolbase = colbase & 4095;
    const int g = lane >> 2;
    const int t4 = lane & 3;
    const bool rotwarp = (region < 2) && ((colbase & 255) == 0) && (wn < 2);

    double invd[4];
    if (rotwarp) {
        #pragma unroll
        for (int nf = 0; nf < 4; nf++)
            invd[nf] = d_invfreq[wn * 16 + nf * 4 + t4];
    }
    const float qscale = (region == 0) ? 0.0625f : 1.0f;
    __half *H = (region == 0) ? Qh : Kh;
    __half *L = (region == 0) ? Ql : Kl;

    #pragma unroll
    for (int mi = 0; mi < 4; mi++) {
        const int rA = rowbase + wm * 64 + mi * 16 + g;
        const int rB = rA + 8;
        int posA = 0, posB = 0;
        if (rotwarp) { posA = pos_ids[rA]; posB = pos_ids[rB]; }
        #pragma unroll
        for (int nf = 0; nf < 4; nf++) {
            float v0 = acc[mi][nf][0], v1 = acc[mi][nf][1];
            float v2 = acc[mi][nf][2], v3 = acc[mi][nf][3];
            if (rotwarp) {
                float angA = (float)((double)posA * invd[nf]);
                float angB = (float)((double)posB * invd[nf]);
                float sA = sinf(angA), cA = cosf(angA);
                float sB = sinf(angB), cB = cosf(angB);
                float t0 = v0 * cA - v1 * sA;
                float t1 = v1 * cA + v0 * sA;
                v0 = t0; v1 = t1;
                t0 = v2 * cB - v3 * sB;
                t1 = v3 * cB + v2 * sB;
                v2 = t0; v3 = t1;
            }
            v0 *= qscale; v1 *= qscale; v2 *= qscale; v3 *= qscale;

            size_t ncol = (size_t)(ncolbase + wn * 32 + nf * 8 + t4 * 2);
            size_t offA = (size_t)rA * HIDDEN + ncol;
            size_t offB = (size_t)rB * HIDDEN + ncol;

            if (region == 2) {
                *(uint32_t*)(Vh + offA) = pack_half(v0, v1);
                *(uint32_t*)(Vh + offB) = pack_half(v2, v3);
            } else {
                __half h0 = __float2half_rn(v0), h1 = __float2half_rn(v1);
                __half h2 = __float2half_rn(v2), h3 = __float2half_rn(v3);
                float l0 = v0 - __half2float(h0), l1 = v1 - __half2float(h1);
                float l2 = v2 - __half2float(h2), l3 = v3 - __half2float(h3);
                *(uint32_t*)(H + offA) = pack_half(__half2float(h0), __half2float(h1));
                *(uint32_t*)(L + offA) = pack_half(l0, l1);
                *(uint32_t*)(H + offB) = pack_half(__half2float(h2), __half2float(h3));
                *(uint32_t*)(L + offB) = pack_half(l2, l3);
            }
        }
    }
}

// ============================================================================
// Wo GEMM, fp16 single-term (R16-proven): C = fp16(O) @ fp16(Wo)^T.
// ============================================================================
#define WO_STAGE (2 * TILE_B)   /* 20480 */

__global__ __launch_bounds__(256, 2) void gemm_wo_fp16_kernel(
    const __half* __restrict__ Ah,
    const __half* __restrict__ Bh, float* __restrict__ C)
{
    extern __shared__ char smg[];
    const uint32_t sb = smem_u32(smg);
    const int tid  = threadIdx.x;
    const int wid  = tid >> 5;
    const int lane = tid & 31;
    const int wm = wid >> 2;
    const int wn = wid & 3;
    const int rowbase = blockIdx.y * 128;
    const int colbase = blockIdx.x * 128;

    const __half* bases[2];
    bases[0] = Ah + (size_t)rowbase * HIDDEN;
    bases[1] = Bh + (size_t)colbase * HIDDEN;

    const int arow = lane & 15;
    const int aoff = ((lane >> 4) & 1) * 16;
    const int brow = (lane & 7) + ((lane >> 4) & 1) * 8;
    const int boff = ((lane >> 3) & 1) * 16;

    float acc[4][4][4];
    #pragma unroll
    for (int i = 0; i < 4; i++)
        #pragma unroll
        for (int j = 0; j < 4; j++)
            #pragma unroll
            for (int q = 0; q < 4; q++) acc[i][j][q] = 0.0f;

    const int NCH = HIDDEN / GBK;
    {
        #pragma unroll
        for (int it = 0; it < 4; it++) {
            int t = tid + it * 256;
            int tile = t >> 9;
            int r    = (t >> 2) & 127;
            int ch   = t & 3;
            const void* gp = bases[tile] + (size_t)r * HIDDEN + ch * 8;
            uint32_t d = sb + tile * TILE_B + r * 80 + ch * 16;
            cp_async16(d, gp);
        }
        CP_COMMIT();
    }
    for (int c = 0; c < NCH; c++) {
        const int p = c & 1;
        CP_WAIT(0);
        __syncthreads();
        if (c + 1 < NCH) {
            const int kb = (c + 1) * GBK;
            #pragma unroll
            for (int it = 0; it < 4; it++) {
                int t = tid + it * 256;
                int tile = t >> 9;
                int r    = (t >> 2) & 127;
                int ch   = t & 3;
                const void* gp = bases[tile] + (size_t)r * HIDDEN + kb + ch * 8;
                uint32_t d = sb + (p ^ 1) * WO_STAGE + tile * TILE_B + r * 80 + ch * 16;
                cp_async16(d, gp);
            }
            CP_COMMIT();
        }
        const uint32_t At_h = sb + p * WO_STAGE;
        const uint32_t Bt_h = At_h + TILE_B;
        #pragma unroll
        for (int ks = 0; ks < 2; ks++) {
            const int kbyte = ks * 32;
            uint32_t ah[4][4];
            #pragma unroll
            for (int mi = 0; mi < 4; mi++) {
                ldsm_x4(ah[mi][0], ah[mi][1], ah[mi][2], ah[mi][3],
                        At_h + (wm * 64 + mi * 16 + arow) * 80 + kbyte + aoff);
            }
            uint32_t bh[4][2];
            #pragma unroll
            for (int nf2 = 0; nf2 < 2; nf2++) {
                uint32_t r0, r1, r2, r3;
                ldsm_x4(r0, r1, r2, r3,
                        Bt_h + (wn * 32 + nf2 * 16 + brow) * 80 + kbyte + boff);
                bh[nf2 * 2][0] = r0; bh[nf2 * 2][1] = r1;
                bh[nf2 * 2 + 1][0] = r2; bh[nf2 * 2 + 1][1] = r3;
            }
            #pragma unroll
            for (int mi = 0; mi < 4; mi++)
                #pragma unroll
                for (int nf = 0; nf < 4; nf++)
                    mma_fp16(acc[mi][nf], ah[mi][0], ah[mi][1], ah[mi][2], ah[mi][3], bh[nf][0], bh[nf][1]);
        }
    }

    const int g = lane >> 2;
    const int t = lane & 3;
    #pragma unroll
    for (int mi = 0; mi < 4; mi++) {
        #pragma unroll
        for (int nf = 0; nf < 4; nf++) {
            float* base = C + (size_t)(rowbase + wm * 64 + mi * 16 + g) * HIDDEN
                            + colbase + wn * 32 + nf * 8 + t * 2;
            *(float2*)base = make_float2(acc[mi][nf][0], acc[mi][nf][1]);
            *(float2*)(base + (size_t)8 * HIDDEN) = make_float2(acc[mi][nf][2], acc[mi][nf][3]);
        }
    }
}

// ============================================================================
// Flash attention: QK fp16x3 (hi/lo, more accurate than bf16x3);
// P fp16-single; V fp16 single (one tile per chunk); O fp16-single.
// ============================================================================
#define AQ   64
#define AKV  64
#define QSTR 528
#define PSTR 144

#define A_QH 0
#define A_QL 33792
#define A_KH 67584
#define A_KL 101376
#define A_VH 135168
#define A_PH 202752
#define A_ST 221184
#define A_SMEM_TOTAL 223488

__global__ __launch_bounds__(256, 1) void attn_mma_kernel(
    const __half* __restrict__ Qh_g, const __half* __restrict__ Ql_g,
    const __half* __restrict__ Kh_g, const __half* __restrict__ Kl_g,
    const __half* __restrict__ Vh_g,
    const float* __restrict__ amask,
    __half* __restrict__ Oh)
{
    extern __shared__ char sma[];
    const uint32_t sb = smem_u32(sma);
    float* pmax   = (float*)(sma + A_ST);
    float* psum   = (float*)(sma + A_ST + 512);
    float* mrow   = (float*)(sma + A_ST + 1024);
    float* lrow   = (float*)(sma + A_ST + 1280);
    float* corr   = (float*)(sma + A_ST + 1536);
    float* mnew   = (float*)(sma + A_ST + 1792);
    float* amask_s= (float*)(sma + A_ST + 2048);

    const int tid  = threadIdx.x;
    const int wid  = tid >> 5;
    const int lane = tid & 31;
    const int qg   = wid & 3;
    const int kvh  = wid >> 2;
    const int dh   = wid >> 2;
    const int qt   = (int)gridDim.x - 1 - (int)blockIdx.x;
    const int h    = blockIdx.y;
    const int b    = blockIdx.z;
    const int q0   = qt * AQ;

    const int g = lane >> 2;
    const int t4 = lane & 3;
    const int arow = lane & 15;
    const int aoff = ((lane >> 4) & 1) * 16;
    const int brow = (lane & 7) + ((lane >> 4) & 1) * 8;
    const int boff = ((lane >> 3) & 1) * 16;
    const int vrow = (lane & 7) + ((lane >> 3) & 1) * 8;
    const int vcoff = (lane >> 4) * 8;

    if (tid < 64) { mrow[tid] = -1e30f; lrow[tid] = 0.0f; }

    {
        const __half* qh = Qh_g + (size_t)(b * SEQ + q0) * HIDDEN + h * 256;
        const __half* ql = Ql_g + (size_t)(b * SEQ + q0) * HIDDEN + h * 256;
        #pragma unroll
        for (int it = 0; it < 8; it++) {
            int t = tid + it * 256;
            int r = t >> 5, c = t & 31;
            cp_async16(sb + A_QH + r * QSTR + c * 16, qh + (size_t)r * HIDDEN + c * 8);
            cp_async16(sb + A_QL + r * QSTR + c * 16, ql + (size_t)r * HIDDEN + c * 8);
        }
    }

    float o[16][4];
    #pragma unroll
    for (int i = 0; i < 16; i++)
        #pragma unroll
        for (int q = 0; q < 4; q++) o[i][q] = 0.0f;

    for (int kc = 0; kc <= qt; kc++) {
        const int k0 = kc * AKV;
        if (kc) __syncthreads();

        {
            const __half* kh = Kh_g + (size_t)(b * SEQ + k0) * HIDDEN + h * 256;
            const __half* kl = Kl_g + (size_t)(b * SEQ + k0) * HIDDEN + h * 256;
            #pragma unroll
            for (int it = 0; it < 8; it++) {
                int t = tid + it * 256;
                int r = t >> 5, c = t & 31;
                cp_async16(sb + A_KH + r * QSTR + c * 16, kh + (size_t)r * HIDDEN + c * 8);
                cp_async16(sb + A_KL + r * QSTR + c * 16, kl + (size_t)r * HIDDEN + c * 8);
            }
            CP_COMMIT();
        }
        {
            const __half* vh = Vh_g + (size_t)(b * SEQ + k0) * HIDDEN + h * 256;
            #pragma unroll
            for (int it = 0; it < 8; it++) {
                int t = tid + it * 256;
                int r = t >> 5, c = t & 31;
                cp_async16(sb + A_VH + r * QSTR + c * 16, vh + (size_t)r * HIDDEN + c * 8);
            }
            CP_COMMIT();
        }
        if (tid < 64) amask_s[tid] = amask[b * SEQ + k0 + tid];

        CP_WAIT(1);
        __syncthreads();

        float s[4][4];
        #pragma unroll
        for (int nt = 0; nt < 4; nt++)
            #pragma unroll
            for (int q = 0; q < 4; q++) s[nt][q] = 0.0f;

        #pragma unroll
        for (int ks = 0; ks < 16; ks++) {
            const int kb = ks * 32;
            uint32_t qah[4], qal[4];
            ldsm_x4(qah[0], qah[1], qah[2], qah[3],
                    sb + A_QH + (qg * 16 + arow) * QSTR + kb + aoff);
            ldsm_x4(qal[0], qal[1], qal[2], qal[3],
                    sb + A_QL + (qg * 16 + arow) * QSTR + kb + aoff);
            uint32_t kbh[4][2], kbl[4][2];
            #pragma unroll
            for (int n2 = 0; n2 < 2; n2++) {
                uint32_t r0, r1, r2, r3;
                ldsm_x4(r0, r1, r2, r3,
                        sb + A_KH + (kvh * 32 + n2 * 16 + brow) * QSTR + kb + boff);
                kbh[n2 * 2][0] = r0; kbh[n2 * 2][1] = r1;
                kbh[n2 * 2 + 1][0] = r2; kbh[n2 * 2 + 1][1] = r3;
                ldsm_x4(r0, r1, r2, r3,
                        sb + A_KL + (kvh * 32 + n2 * 16 + brow) * QSTR + kb + boff);
                kbl[n2 * 2][0] = r0; kbl[n2 * 2][1] = r1;
                kbl[n2 * 2 + 1][0] = r2; kbl[n2 * 2 + 1][1] = r3;
            }
            #pragma unroll
            for (int nt = 0; nt < 4; nt++) {
                mma_fp16(s[nt], qah[0], qah[1], qah[2], qah[3], kbh[nt][0], kbh[nt][1]);
                mma_fp16(s[nt], qah[0], qah[1], qah[2], qah[3], kbl[nt][0], kbl[nt][1]);
                mma_fp16(s[nt], qal[0], qal[1], qal[2], qal[3], kbh[nt][0], kbh[nt][1]);
            }
        }

        const int rA = q0 + qg * 16 + g;
        const int rB = rA + 8;
        #pragma unroll
        for (int nt = 0; nt < 4; nt++) {
            int lc = kvh * 32 + nt * 8 + t4 * 2;
            int cg = k0 + lc;
            bool p0 = amask_s[lc] > 0.0f;
            bool p1 = amask_s[lc + 1] > 0.0f;
            if (cg > rA || !p0)     s[nt][0] = -1e30f;
            if (cg + 1 > rA || !p1) s[nt][1] = -1e30f;
            if (cg > rB || !p0)     s[nt][2] = -1e30f;
            if (cg + 1 > rB || !p1) s[nt][3] = -1e30f;
        }

        float mA = -1e30f, mB = -1e30f;
        #pragma unroll
        for (int nt = 0; nt < 4; nt++) {
            mA = fmaxf(mA, fmaxf(s[nt][0], s[nt][1]));
            mB = fmaxf(mB, fmaxf(s[nt][2], s[nt][3]));
        }
        mA = fmaxf(mA, __shfl_xor_sync(0xffffffffu, mA, 1));
        mA = fmaxf(mA, __shfl_xor_sync(0xffffffffu, mA, 2));
        mB = fmaxf(mB, __shfl_xor_sync(0xffffffffu, mB, 1));
        mB = fmaxf(mB, __shfl_xor_sync(0xffffffffu, mB, 2));
        if (t4 == 0) {
            pmax[kvh * 64 + qg * 16 + g] = mA;
            pmax[kvh * 64 + qg * 16 + g + 8] = mB;
        }
        __syncthreads();

        if (tid < 64) {
            float mo = mrow[tid];
            float pm = fmaxf(pmax[tid], pmax[64 + tid]);
            float mn = fmaxf(mo, pm);
            mnew[tid] = mn;
            corr[tid] = __expf(mo - mn);
            mrow[tid] = mn;
        }
        __syncthreads();

        {
            float mnA = mnew[qg * 16 + g];
            float mnB = mnew[qg * 16 + g + 8];
            float sA = 0.0f, sB = 0.0f;
            #pragma unroll
            for (int nt = 0; nt < 4; nt++) {
                float p0 = __expf(s[nt][0] - mnA);
                float p1 = __expf(s[nt][1] - mnA);
                float p2 = __expf(s[nt][2] - mnB);
                float p3 = __expf(s[nt][3] - mnB);
                sA += p0 + p1;
                sB += p2 + p3;
                uint32_t cb = (kvh * 32 + nt * 8 + t4 * 2) * 2;
                uint32_t adrA = (qg * 16 + g) * PSTR + cb;
                uint32_t adrB = (qg * 16 + g + 8) * PSTR + cb;
                *(uint32_t*)(sma + A_PH + adrA) = pack_half(p0, p1);
                *(uint32_t*)(sma + A_PH + adrB) = pack_half(p2, p3);
            }
            sA += __shfl_xor_sync(0xffffffffu, sA, 1);
            sA += __shfl_xor_sync(0xffffffffu, sA, 2);
            sB += __shfl_xor_sync(0xffffffffu, sB, 1);
            sB += __shfl_xor_sync(0xffffffffu, sB, 2);
            if (t4 == 0) {
                psum[kvh * 64 + qg * 16 + g] = sA;
                psum[kvh * 64 + qg * 16 + g + 8] = sB;
            }
        }
        CP_WAIT(0);
        __syncthreads();

        if (tid < 64)
            lrow[tid] = lrow[tid] * corr[tid] + psum[tid] + psum[64 + tid];

        {
            float cA = corr[qg * 16 + g];
            float cB = corr[qg * 16 + g + 8];
            #pragma unroll
            for (int nt = 0; nt < 16; nt++) {
                o[nt][0] *= cA; o[nt][1] *= cA;
                o[nt][2] *= cB; o[nt][3] *= cB;
            }
        }
        #pragma unroll
        for (int ks = 0; ks < 4; ks++) {
            uint32_t pah[4];
            ldsm_x4(pah[0], pah[1], pah[2], pah[3],
                    sb + A_PH + (qg * 16 + arow) * PSTR + ks * 32 + aoff);
            #pragma unroll
            for (int np = 0; np < 8; np++) {
                int col = dh * 128 + np * 16 + vcoff;
                uint32_t vrowg = (ks * 16 + vrow) * QSTR + col * 2;
                uint32_t vh0, vh1, vh2, vh3;
                ldsm_x4_t(vh0, vh1, vh2, vh3, sb + A_VH + vrowg);
                mma_fp16(o[np * 2], pah[0], pah[1], pah[2], pah[3], vh0, vh1);
                mma_fp16(o[np * 2 + 1], pah[0], pah[1], pah[2], pah[3], vh2, vh3);
            }
        }
    }

    __syncthreads();
    {
        float invA = 1.0f / lrow[qg * 16 + g];
        float invB = 1.0f / lrow[qg * 16 + g + 8];
        size_t rowA = (size_t)(b * SEQ + q0 + qg * 16 + g) * HIDDEN;
        size_t rowB = rowA + (size_t)8 * HIDDEN;
        int colbase = h * 256 + dh * 128 + t4 * 2;
        #pragma unroll
        for (int nt = 0; nt < 16; nt++) {
            int col = colbase + nt * 8;
            *(uint32_t*)(Oh + rowA + col) = pack_half(o[nt][0] * invA, o[nt][1] * invA);
            *(uint32_t*)(Oh + rowB + col) = pack_half(o[nt][2] * invB, o[nt][3] * invB);
        }
    }
}

// ============================================================================
// Launch
// ============================================================================
extern "C" void kernel_launch(void* const* d_in, const int* in_sizes, int n_in,
                              void* d_out, int out_size)
{
    const float* X   = (const float*)d_in[0];
    const float* msk = (const float*)d_in[1];
    const int*   pos = (const int*)  d_in[2];
    const float* Wq  = (const float*)d_in[3];
    const float* Wk  = (const float*)d_in[4];
    const float* Wv  = (const float*)d_in[5];
    const float* Wo  = (const float*)d_in[6];
    float* out = (float*)d_out;

    __nv_bfloat16* bf = nullptr;
    cudaGetSymbolAddress((void**)&bf, g_bf16);

    __half* Xh    = (__half*)(bf + 0 * SLOT);
    __half* Xl    = (__half*)(bf + 1 * SLOT);
    __half* Oh16  = (__half*)(bf + 2 * SLOT);
    __half* WqkvH = (__half*)(bf + 4 * SLOT);
    __half* WqkvL = (__half*)(bf + 7 * SLOT);
    __half* Wo16  = (__half*)(bf + 10 * SLOT);
    __half* Qh    = (__half*)(bf + 12 * SLOT);
    __half* Ql    = (__half*)(bf + 13 * SLOT);
    __half* Kh    = (__half*)(bf + 14 * SLOT);
    __half* Kl    = (__half*)(bf + 15 * SLOT);
    __half* Vh    = (__half*)(bf + 16 * SLOT);

    dim3 sgrid(HIDDEN / 32, HIDDEN / 32, 5);
    split_all_kernel<<<sgrid, 256>>>(X, Wq, Wk, Wv, Wo,
                                     Xh, Xl, WqkvH, WqkvL, Wo16);

    int gsmem = 2 * STAGE_B;     // 81920
    int wsmem = 2 * WO_STAGE;    // 40960
    cudaFuncSetAttribute(gemm_qkv_kernel,
                         cudaFuncAttributeMaxDynamicSharedMemorySize, gsmem);
    cudaFuncSetAttribute(gemm_wo_fp16_kernel,
                         cudaFuncAttributeMaxDynamicSharedMemorySize, wsmem);

    dim3 qkvgrid(3 * HIDDEN / 128, MROWS / 128);   // (96, 32)
    gemm_qkv_kernel<<<qkvgrid, 256, gsmem>>>(Xh, Xl, WqkvH, WqkvL, pos,
                                             Qh, Ql, Kh, Kl, Vh);

    cudaFuncSetAttribute(attn_mma_kernel,
                         cudaFuncAttributeMaxDynamicSharedMemorySize, A_SMEM_TOTAL);
    dim3 agrid(SEQ / AQ, NHEADS, BATCH);
    attn_mma_kernel<<<agrid, 256, A_SMEM_TOTAL>>>(Qh, Ql, Kh, Kl, Vh, msk, Oh16);

    dim3 ogrid(HIDDEN / 128, MROWS / 128);   // (32, 32)
    gemm_wo_fp16_kernel<<<ogrid, 256, wsmem>>>(Oh16, Wo16, out);
}